// round 4
// baseline (speedup 1.0000x reference)
#include <cuda_runtime.h>
#include <cuda_bf16.h>
#include <cstdint>
#include <cmath>

#define B_   8
#define LQ   1024
#define LK   8192
#define D_   256
#define DC   128
#define EPSF 1e-6f
#define LN2F 0.69314718055994531f

// ---------------- scratch (no allocations allowed) ----------------
__device__ __nv_bfloat16  g_qt[B_ * LQ * DC];     // q~ = q @ W_up     (2 MB)
__device__ float          g_qsq[B_ * LQ];
__device__ __nv_bfloat16  g_kc[B_ * LK * DC];     // dequantized codes (16 MB)
__device__ float          g_ksq[B_ * LK];
__device__ __nv_bfloat16  g_G[DC * DC];           // G = W^T W (bf16)
__device__ __nv_bfloat16  g_Wt[DC * D_];          // W^T (c-major): Wt[c][d] = W[d][c]

// ---------------- fast math ----------------
__device__ __forceinline__ float fast_rcp(float x)  { float r; asm("rcp.approx.f32 %0, %1;"  : "=f"(r) : "f"(x)); return r; }
__device__ __forceinline__ float fast_sqrt(float x) { float r; asm("sqrt.approx.f32 %0, %1;" : "=f"(r) : "f"(x)); return r; }
__device__ __forceinline__ float fast_lg2(float x)  { float r; asm("lg2.approx.f32 %0, %1;"  : "=f"(r) : "f"(x)); return r; }

// ---------------- mma helpers ----------------
__device__ __forceinline__ uint32_t sptr(const void* p) {
    return (uint32_t)__cvta_generic_to_shared(p);
}
__device__ __forceinline__ void ldsm4(uint32_t& a0, uint32_t& a1, uint32_t& a2, uint32_t& a3, uint32_t addr) {
    asm volatile("ldmatrix.sync.aligned.m8n8.x4.shared.b16 {%0,%1,%2,%3}, [%4];"
                 : "=r"(a0), "=r"(a1), "=r"(a2), "=r"(a3) : "r"(addr));
}
__device__ __forceinline__ void ldsm2(uint32_t& b0, uint32_t& b1, uint32_t addr) {
    asm volatile("ldmatrix.sync.aligned.m8n8.x2.shared.b16 {%0,%1}, [%2];"
                 : "=r"(b0), "=r"(b1) : "r"(addr));
}
__device__ __forceinline__ void mma16816(float& c0, float& c1, float& c2, float& c3,
                                         uint32_t a0, uint32_t a1, uint32_t a2, uint32_t a3,
                                         uint32_t b0, uint32_t b1) {
    asm volatile("mma.sync.aligned.m16n8k16.row.col.f32.bf16.bf16.f32 "
                 "{%0,%1,%2,%3}, {%4,%5,%6,%7}, {%8,%9}, {%0,%1,%2,%3};"
                 : "+f"(c0), "+f"(c1), "+f"(c2), "+f"(c3)
                 : "r"(a0), "r"(a1), "r"(a2), "r"(a3), "r"(b0), "r"(b1));
}

// ---------------- kernel 1: G = W^T W (bf16) + Wt bf16 ----------------
__global__ void k_G(const float* __restrict__ W) {
    __shared__ float col[D_];
    __shared__ float red[256];
    const int c1 = blockIdx.x;          // 128 blocks
    const int t  = threadIdx.x;         // 256 threads
    const int c2 = t & 127, h = t >> 7;

    float wv = W[t * DC + c1];
    col[t] = wv;
    g_Wt[c1 * D_ + t] = __float2bfloat16(wv);
    __syncthreads();

    float acc = 0.f;
    const int d0 = h * 128;
    #pragma unroll 8
    for (int d = 0; d < 128; d++) acc += col[d0 + d] * W[(d0 + d) * DC + c2];
    red[t] = acc;
    __syncthreads();
    if (h == 0) g_G[c1 * DC + c2] = __float2bfloat16(red[c2] + red[c2 + 128]);
}

// ---------------- kernel 2: q~ = q @ W via MMA + q_sq ----------------
#define QSTRIDE 264
#define SMEM_PREPQ (128 * QSTRIDE * 2 * 2 + 256 * 4 + 128 * 4 + 256)

__global__ void k_prepq(const float* __restrict__ q) {
    extern __shared__ char sm[];
    __nv_bfloat16* qs  = (__nv_bfloat16*)sm;               // [128][264] bf16
    __nv_bfloat16* Wts = qs + 128 * QSTRIDE;               // [128][264] bf16
    float*         par = (float*)(Wts + 128 * QSTRIDE);    // [256]
    float*         qsq = par + 256;                        // [128]

    const int t  = threadIdx.x;          // 256
    const int r0 = blockIdx.x * 128;     // 64 blocks

    {
        const float4* src = (const float4*)(q + (size_t)r0 * D_);
        #pragma unroll
        for (int i = 0; i < 32; i++) {
            int idx = t + i * 256;
            int row = idx >> 6, c4 = (idx & 63) * 4;
            float4 v = src[idx];
            *(__nv_bfloat162*)&qs[row * QSTRIDE + c4]     = __floats2bfloat162_rn(v.x, v.y);
            *(__nv_bfloat162*)&qs[row * QSTRIDE + c4 + 2] = __floats2bfloat162_rn(v.z, v.w);
        }
    }
    {
        const float4* rowp = (const float4*)(q + (size_t)(r0 + (t >> 1)) * D_) + (t & 1) * 32;
        float ss = 0.f;
        #pragma unroll 8
        for (int i = 0; i < 32; i++) {
            float4 v = rowp[i];
            ss += v.x * v.x + v.y * v.y + v.z * v.z + v.w * v.w;
        }
        par[t] = ss;
    }
    {
        #pragma unroll
        for (int i = 0; i < 16; i++) {
            int idx = t + i * 256;
            int r = idx >> 5, c8 = (idx & 31) * 8;
            *(uint4*)&Wts[r * QSTRIDE + c8] = ((const uint4*)g_Wt)[idx];
        }
    }
    __syncthreads();
    if (t < 128) qsq[t] = par[2 * t] + par[2 * t + 1];

    const int w = t >> 5, lane = t & 31;
    const int m0 = (w >> 2) * 64, n0 = (w & 3) * 32;
    const int gid = lane >> 2, tid2 = lane & 3;
    const int arow = lane & 15, acol = ((lane >> 4) << 3);
    const int brow = lane & 7,  bcol = (((lane >> 3) & 1) << 3);

    float acc[4][4][4];
    #pragma unroll
    for (int i = 0; i < 4; i++)
        #pragma unroll
        for (int j = 0; j < 4; j++)
            #pragma unroll
            for (int c = 0; c < 4; c++) acc[i][j][c] = 0.f;

    #pragma unroll
    for (int ks = 0; ks < 16; ks++) {
        const int k0 = ks * 16;
        uint32_t A[4][4], Bf[4][2];
        #pragma unroll
        for (int ms = 0; ms < 4; ms++)
            ldsm4(A[ms][0], A[ms][1], A[ms][2], A[ms][3],
                  sptr(&qs[(m0 + ms * 16 + arow) * QSTRIDE + k0 + acol]));
        #pragma unroll
        for (int ns = 0; ns < 4; ns++)
            ldsm2(Bf[ns][0], Bf[ns][1],
                  sptr(&Wts[(n0 + ns * 8 + brow) * QSTRIDE + k0 + bcol]));
        #pragma unroll
        for (int ms = 0; ms < 4; ms++)
            #pragma unroll
            for (int ns = 0; ns < 4; ns++)
                mma16816(acc[ms][ns][0], acc[ms][ns][1], acc[ms][ns][2], acc[ms][ns][3],
                         A[ms][0], A[ms][1], A[ms][2], A[ms][3], Bf[ns][0], Bf[ns][1]);
    }

    #pragma unroll
    for (int ms = 0; ms < 4; ms++) {
        const int rA = m0 + ms * 16 + gid, rB = rA + 8;
        #pragma unroll
        for (int ns = 0; ns < 4; ns++) {
            const int c0 = n0 + ns * 8 + tid2 * 2;
            *(__nv_bfloat162*)&g_qt[(size_t)(r0 + rA) * DC + c0] =
                __floats2bfloat162_rn(acc[ms][ns][0], acc[ms][ns][1]);
            *(__nv_bfloat162*)&g_qt[(size_t)(r0 + rB) * DC + c0] =
                __floats2bfloat162_rn(acc[ms][ns][2], acc[ms][ns][3]);
        }
    }
    __syncthreads();
    if (t < 128) g_qsq[r0 + t] = qsq[t];
}

// ---------------- kernel 3: dequant codes + k_sq = kc^T G kc ----------------
#define PSTRIDE 136
#define SMEM_PREPK (2 * 128 * PSTRIDE * 2 + 512)

__global__ void k_prepk(const int* __restrict__ kq,
                        const float* __restrict__ kscale,
                        const float* __restrict__ kzero) {
    extern __shared__ char sm[];
    __nv_bfloat16* kcs  = (__nv_bfloat16*)sm;                 // [128][136]
    __nv_bfloat16* Gs   = kcs + 128 * PSTRIDE;                // [128][136]
    float*         ksqs = (float*)(Gs + 128 * PSTRIDE);       // [128]

    const int t    = threadIdx.x;        // 256
    const int row0 = blockIdx.x * 128;
    const int b    = row0 / LK;

    {
        const int c4 = (t & 31) * 4;
        const float4 sc = *(const float4*)(kscale + b * DC + c4);
        const float4 zr = *(const float4*)(kzero + b * DC + c4);
        const int rb = t >> 5;
        #pragma unroll
        for (int i = 0; i < 16; i++) {
            const int r = rb + i * 8;
            const int4 code = *(const int4*)(kq + (size_t)(row0 + r) * DC + c4);
            __nv_bfloat162 p0, p1;
            p0.x = __float2bfloat16(sc.x * ((float)code.x - zr.x));
            p0.y = __float2bfloat16(sc.y * ((float)code.y - zr.y));
            p1.x = __float2bfloat16(sc.z * ((float)code.z - zr.z));
            p1.y = __float2bfloat16(sc.w * ((float)code.w - zr.w));
            *(__nv_bfloat162*)&kcs[r * PSTRIDE + c4]     = p0;
            *(__nv_bfloat162*)&kcs[r * PSTRIDE + c4 + 2] = p1;
            *(__nv_bfloat162*)&g_kc[(size_t)(row0 + r) * DC + c4]     = p0;
            *(__nv_bfloat162*)&g_kc[(size_t)(row0 + r) * DC + c4 + 2] = p1;
        }
    }
    {
        const int r = t >> 1, ch = (t & 1) * 64;
        const uint4* src = (const uint4*)(g_G + r * DC + ch);
        #pragma unroll
        for (int i = 0; i < 8; i++) *(uint4*)&Gs[r * PSTRIDE + ch + i * 8] = src[i];
    }
    if (t < 128) ksqs[t] = 0.f;
    __syncthreads();

    const int w = t >> 5, lane = t & 31;
    const int m0 = (w >> 2) * 64, n0 = (w & 3) * 32;
    const int gid = lane >> 2, tid2 = lane & 3;
    const int arow = lane & 15, acol = ((lane >> 4) << 3);
    const int brow = lane & 7,  bcol = (((lane >> 3) & 1) << 3);

    float acc[4][4][4];
    #pragma unroll
    for (int i = 0; i < 4; i++)
        #pragma unroll
        for (int j = 0; j < 4; j++)
            #pragma unroll
            for (int c = 0; c < 4; c++) acc[i][j][c] = 0.f;

    #pragma unroll
    for (int ks = 0; ks < 8; ks++) {
        const int k0 = ks * 16;
        uint32_t A[4][4], Bf[4][2];
        #pragma unroll
        for (int ms = 0; ms < 4; ms++)
            ldsm4(A[ms][0], A[ms][1], A[ms][2], A[ms][3],
                  sptr(&kcs[(m0 + ms * 16 + arow) * PSTRIDE + k0 + acol]));
        #pragma unroll
        for (int ns = 0; ns < 4; ns++)
            ldsm2(Bf[ns][0], Bf[ns][1],
                  sptr(&Gs[(n0 + ns * 8 + brow) * PSTRIDE + k0 + bcol]));
        #pragma unroll
        for (int ms = 0; ms < 4; ms++)
            #pragma unroll
            for (int ns = 0; ns < 4; ns++)
                mma16816(acc[ms][ns][0], acc[ms][ns][1], acc[ms][ns][2], acc[ms][ns][3],
                         A[ms][0], A[ms][1], A[ms][2], A[ms][3], Bf[ns][0], Bf[ns][1]);
    }

    #pragma unroll
    for (int ms = 0; ms < 4; ms++) {
        const int rA = m0 + ms * 16 + gid, rB = rA + 8;
        float sA = 0.f, sB = 0.f;
        #pragma unroll
        for (int ns = 0; ns < 4; ns++) {
            const int c0 = n0 + ns * 8 + tid2 * 2;
            sA += acc[ms][ns][0] * __bfloat162float(kcs[rA * PSTRIDE + c0]);
            sA += acc[ms][ns][1] * __bfloat162float(kcs[rA * PSTRIDE + c0 + 1]);
            sB += acc[ms][ns][2] * __bfloat162float(kcs[rB * PSTRIDE + c0]);
            sB += acc[ms][ns][3] * __bfloat162float(kcs[rB * PSTRIDE + c0 + 1]);
        }
        atomicAdd(&ksqs[rA], sA);
        atomicAdd(&ksqs[rB], sB);
    }
    __syncthreads();
    if (t < 128) g_ksq[row0 + t] = ksqs[t];
}

// ---------------- kernel 4: main — 128x64 tile, 4 CTAs/SM ----------------
#define KTILE 64
#define SMEM_MAIN (128 * PSTRIDE * 2 + KTILE * PSTRIDE * 2 + 2 * 128 * 4 + 2 * KTILE * 4 + 256)

__global__ void __launch_bounds__(256, 4) k_main(float* __restrict__ out) {
    extern __shared__ char sm[];
    __nv_bfloat16* qts  = (__nv_bfloat16*)sm;              // [128][136]
    __nv_bfloat16* kcs  = qts + 128 * PSTRIDE;             // [64][136]
    float*         qsqs = (float*)(kcs + KTILE * PSTRIDE); // [128]
    float*         rqs  = qsqs + 128;                      // [128]
    float*         ksqs = rqs + 128;                       // [64]
    float*         rks  = ksqs + KTILE;                    // [64]

    const int t = threadIdx.x;                             // 256
    const int kb = blockIdx.x, qb = blockIdx.y, b = blockIdx.z;
    const int q0 = qb * 128, k0t = kb * KTILE;

    // load q tile: 128 rows x 256B; 2 threads/row
    {
        const int r = t >> 1, ch = (t & 1) * 64;
        const uint4* s1 = (const uint4*)(g_qt + ((size_t)(b * LQ + q0 + r)) * DC + ch);
        #pragma unroll
        for (int i = 0; i < 8; i++) *(uint4*)&qts[r * PSTRIDE + ch + i * 8] = s1[i];
    }
    // load k tile: 64 rows x 256B; 4 threads/row
    {
        const int r = t >> 2, ch = (t & 3) * 32;
        const uint4* s2 = (const uint4*)(g_kc + ((size_t)(b * LK + k0t + r)) * DC + ch);
        #pragma unroll
        for (int i = 0; i < 4; i++) *(uint4*)&kcs[r * PSTRIDE + ch + i * 8] = s2[i];
    }
    if (t < 128) {
        float qs = g_qsq[b * LQ + q0 + t];
        qsqs[t] = qs;
        rqs[t]  = 1.f - fminf(qs, 1.f - EPSF);
    } else if (t < 128 + KTILE) {
        int i = t - 128;
        float ks = g_ksq[b * LK + k0t + i];
        ksqs[i] = ks;
        rks[i]  = 1.f - fminf(ks, 1.f - EPSF);
    }
    __syncthreads();

    // warp layout: 4 x 2 warps of 32(m) x 32(n)
    const int w = t >> 5, lane = t & 31;
    const int m0 = (w & 3) * 32, n0 = (w >> 2) * 32;
    const int gid = lane >> 2, tid2 = lane & 3;
    const int arow = lane & 15, acol = ((lane >> 4) << 3);
    const int brow = lane & 7,  bcol = (((lane >> 3) & 1) << 3);

    float acc[2][4][4];
    #pragma unroll
    for (int i = 0; i < 2; i++)
        #pragma unroll
        for (int j = 0; j < 4; j++)
            #pragma unroll
            for (int c = 0; c < 4; c++) acc[i][j][c] = 0.f;

    #pragma unroll
    for (int ks = 0; ks < 8; ks++) {
        const int k0 = ks * 16;
        uint32_t A[2][4], Bf[4][2];
        #pragma unroll
        for (int ms = 0; ms < 2; ms++)
            ldsm4(A[ms][0], A[ms][1], A[ms][2], A[ms][3],
                  sptr(&qts[(m0 + ms * 16 + arow) * PSTRIDE + k0 + acol]));
        #pragma unroll
        for (int ns = 0; ns < 4; ns++)
            ldsm2(Bf[ns][0], Bf[ns][1],
                  sptr(&kcs[(n0 + ns * 8 + brow) * PSTRIDE + k0 + bcol]));
        #pragma unroll
        for (int ms = 0; ms < 2; ms++)
            #pragma unroll
            for (int ns = 0; ns < 4; ns++)
                mma16816(acc[ms][ns][0], acc[ms][ns][1], acc[ms][ns][2], acc[ms][ns][3],
                         A[ms][0], A[ms][1], A[ms][2], A[ms][3], Bf[ns][0], Bf[ns][1]);
    }

    // distance epilogue + direct streaming stores
    #pragma unroll
    for (int ms = 0; ms < 2; ms++) {
        const int rA = m0 + ms * 16 + gid, rB = rA + 8;
        const float qsA = qsqs[rA], qsB = qsqs[rB];
        const float rqA = rqs[rA],  rqB = rqs[rB];
        const size_t baseA = ((size_t)(b * LQ + q0 + rA)) * LK + k0t;
        const size_t baseB = baseA + (size_t)8 * LK;
        #pragma unroll
        for (int ns = 0; ns < 4; ns++) {
            const int c0 = n0 + ns * 8 + tid2 * 2;
            const float ks0 = ksqs[c0], ks1 = ksqs[c0 + 1];
            const float rk0 = rks[c0],  rk1 = rks[c0 + 1];

            float u[4], dn[4], dist[4];
            u[0] = 2.f * fmaxf(fmaf(-2.f, acc[ms][ns][0], qsA + ks0), 0.f); dn[0] = fmaf(rqA, rk0, EPSF);
            u[1] = 2.f * fmaxf(fmaf(-2.f, acc[ms][ns][1], qsA + ks1), 0.f); dn[1] = fmaf(rqA, rk1, EPSF);
            u[2] = 2.f * fmaxf(fmaf(-2.f, acc[ms][ns][2], qsB + ks0), 0.f); dn[2] = fmaf(rqB, rk0, EPSF);
            u[3] = 2.f * fmaxf(fmaf(-2.f, acc[ms][ns][3], qsB + ks1), 0.f); dn[3] = fmaf(rqB, rk1, EPSF);

            bool bad = false;
            #pragma unroll
            for (int j = 0; j < 4; j++) {
                // acosh(1+t), t = u/dn >> 1:  ln2*(1 + lg2(u+dn) - lg2(dn))
                dist[j] = LN2F * (1.f + fast_lg2(u[j] + dn[j]) - fast_lg2(dn[j]));
                bad |= (u[j] < 100.f * dn[j]);
            }
            if (bad) {       // exact path (cold)
                #pragma unroll
                for (int j = 0; j < 4; j++) {
                    float tt = u[j] * fast_rcp(dn[j]);
                    float s  = fast_sqrt(fmaf(tt, tt, 2.f * tt));
                    dist[j] = LN2F * fast_lg2(1.f + tt + s);
                }
            }
            __stcs((float2*)(out + baseA + c0), make_float2(dist[0], dist[1]));
            __stcs((float2*)(out + baseB + c0), make_float2(dist[2], dist[3]));
        }
    }
}

// ---------------- launch ----------------
extern "C" void kernel_launch(void* const* d_in, const int* in_sizes, int n_in,
                              void* d_out, int out_size) {
    const float* q   = (const float*)d_in[0];
    const int*   kq  = (const int*)d_in[1];
    const float* ksc = (const float*)d_in[2];
    const float* kz  = (const float*)d_in[3];
    const float* W   = (const float*)d_in[4];
    float* out = (float*)d_out;
    (void)in_sizes; (void)n_in; (void)out_size;

    cudaFuncSetAttribute(k_prepq, cudaFuncAttributeMaxDynamicSharedMemorySize, SMEM_PREPQ);
    cudaFuncSetAttribute(k_prepk, cudaFuncAttributeMaxDynamicSharedMemorySize, SMEM_PREPK);
    cudaFuncSetAttribute(k_main,  cudaFuncAttributeMaxDynamicSharedMemorySize, SMEM_MAIN);

    k_G<<<DC, 256>>>(W);
    k_prepq<<<(B_ * LQ) / 128, 256, SMEM_PREPQ>>>(q);
    k_prepk<<<(B_ * LK) / 128, 256, SMEM_PREPK>>>(kq, ksc, kz);
    k_main<<<dim3(LK / KTILE, LQ / 128, B_), 256, SMEM_MAIN>>>(out);
}

// round 5
// speedup vs baseline: 1.1735x; 1.1735x over previous
#include <cuda_runtime.h>
#include <cuda_bf16.h>
#include <cstdint>
#include <cmath>

#define B_   8
#define LQ   1024
#define LK   8192
#define D_   256
#define DC   128
#define EPSF 1e-6f
#define LN2F 0.69314718055994531f

// ---------------- scratch (no allocations allowed) ----------------
__device__ __nv_bfloat16  g_qt[B_ * LQ * DC];     // q~ = q @ W_up     (2 MB)
__device__ float          g_qsq[B_ * LQ];
__device__ __nv_bfloat16  g_kc[B_ * LK * DC];     // dequantized codes (16 MB)
__device__ float          g_ksq[B_ * LK];
__device__ __nv_bfloat16  g_G[DC * DC];           // G = W^T W (bf16)
__device__ __nv_bfloat16  g_Wt[DC * D_];          // W^T (c-major)

// ---------------- fast math ----------------
__device__ __forceinline__ float fast_rcp(float x)  { float r; asm("rcp.approx.f32 %0, %1;"  : "=f"(r) : "f"(x)); return r; }
__device__ __forceinline__ float fast_sqrt(float x) { float r; asm("sqrt.approx.f32 %0, %1;" : "=f"(r) : "f"(x)); return r; }
__device__ __forceinline__ float fast_lg2(float x)  { float r; asm("lg2.approx.f32 %0, %1;"  : "=f"(r) : "f"(x)); return r; }

// ---------------- mma helpers ----------------
__device__ __forceinline__ uint32_t sptr(const void* p) {
    return (uint32_t)__cvta_generic_to_shared(p);
}
__device__ __forceinline__ void ldsm4(uint32_t& a0, uint32_t& a1, uint32_t& a2, uint32_t& a3, uint32_t addr) {
    asm volatile("ldmatrix.sync.aligned.m8n8.x4.shared.b16 {%0,%1,%2,%3}, [%4];"
                 : "=r"(a0), "=r"(a1), "=r"(a2), "=r"(a3) : "r"(addr));
}
__device__ __forceinline__ void ldsm2(uint32_t& b0, uint32_t& b1, uint32_t addr) {
    asm volatile("ldmatrix.sync.aligned.m8n8.x2.shared.b16 {%0,%1}, [%2];"
                 : "=r"(b0), "=r"(b1) : "r"(addr));
}
__device__ __forceinline__ void mma16816(float& c0, float& c1, float& c2, float& c3,
                                         uint32_t a0, uint32_t a1, uint32_t a2, uint32_t a3,
                                         uint32_t b0, uint32_t b1) {
    asm volatile("mma.sync.aligned.m16n8k16.row.col.f32.bf16.bf16.f32 "
                 "{%0,%1,%2,%3}, {%4,%5,%6,%7}, {%8,%9}, {%0,%1,%2,%3};"
                 : "+f"(c0), "+f"(c1), "+f"(c2), "+f"(c3)
                 : "r"(a0), "r"(a1), "r"(a2), "r"(a3), "r"(b0), "r"(b1));
}

// ---------------- kernel 1: G = W^T W (bf16) + Wt bf16 ----------------
__global__ void k_G(const float* __restrict__ W) {
    __shared__ float col[D_];
    __shared__ float red[256];
    const int c1 = blockIdx.x;
    const int t  = threadIdx.x;
    const int c2 = t & 127, h = t >> 7;

    float wv = W[t * DC + c1];
    col[t] = wv;
    g_Wt[c1 * D_ + t] = __float2bfloat16(wv);
    __syncthreads();

    float acc = 0.f;
    const int d0 = h * 128;
    #pragma unroll 8
    for (int d = 0; d < 128; d++) acc += col[d0 + d] * W[(d0 + d) * DC + c2];
    red[t] = acc;
    __syncthreads();
    if (h == 0) g_G[c1 * DC + c2] = __float2bfloat16(red[c2] + red[c2 + 128]);
}

// ---------------- kernel 2: q~ = q @ W via MMA + q_sq ----------------
#define QSTRIDE 264
#define SMEM_PREPQ (128 * QSTRIDE * 2 * 2 + 256 * 4 + 128 * 4 + 256)

__global__ void k_prepq(const float* __restrict__ q) {
    extern __shared__ char sm[];
    __nv_bfloat16* qs  = (__nv_bfloat16*)sm;
    __nv_bfloat16* Wts = qs + 128 * QSTRIDE;
    float*         par = (float*)(Wts + 128 * QSTRIDE);
    float*         qsq = par + 256;

    const int t  = threadIdx.x;
    const int r0 = blockIdx.x * 128;

    {
        const float4* src = (const float4*)(q + (size_t)r0 * D_);
        #pragma unroll
        for (int i = 0; i < 32; i++) {
            int idx = t + i * 256;
            int row = idx >> 6, c4 = (idx & 63) * 4;
            float4 v = src[idx];
            *(__nv_bfloat162*)&qs[row * QSTRIDE + c4]     = __floats2bfloat162_rn(v.x, v.y);
            *(__nv_bfloat162*)&qs[row * QSTRIDE + c4 + 2] = __floats2bfloat162_rn(v.z, v.w);
        }
    }
    {
        const float4* rowp = (const float4*)(q + (size_t)(r0 + (t >> 1)) * D_) + (t & 1) * 32;
        float ss = 0.f;
        #pragma unroll 8
        for (int i = 0; i < 32; i++) {
            float4 v = rowp[i];
            ss += v.x * v.x + v.y * v.y + v.z * v.z + v.w * v.w;
        }
        par[t] = ss;
    }
    {
        #pragma unroll
        for (int i = 0; i < 16; i++) {
            int idx = t + i * 256;
            int r = idx >> 5, c8 = (idx & 31) * 8;
            *(uint4*)&Wts[r * QSTRIDE + c8] = ((const uint4*)g_Wt)[idx];
        }
    }
    __syncthreads();
    if (t < 128) qsq[t] = par[2 * t] + par[2 * t + 1];

    const int w = t >> 5, lane = t & 31;
    const int m0 = (w >> 2) * 64, n0 = (w & 3) * 32;
    const int gid = lane >> 2, tid2 = lane & 3;
    const int arow = lane & 15, acol = ((lane >> 4) << 3);
    const int brow = lane & 7,  bcol = (((lane >> 3) & 1) << 3);

    float acc[4][4][4];
    #pragma unroll
    for (int i = 0; i < 4; i++)
        #pragma unroll
        for (int j = 0; j < 4; j++)
            #pragma unroll
            for (int c = 0; c < 4; c++) acc[i][j][c] = 0.f;

    #pragma unroll
    for (int ks = 0; ks < 16; ks++) {
        const int k0 = ks * 16;
        uint32_t A[4][4], Bf[4][2];
        #pragma unroll
        for (int ms = 0; ms < 4; ms++)
            ldsm4(A[ms][0], A[ms][1], A[ms][2], A[ms][3],
                  sptr(&qs[(m0 + ms * 16 + arow) * QSTRIDE + k0 + acol]));
        #pragma unroll
        for (int ns = 0; ns < 4; ns++)
            ldsm2(Bf[ns][0], Bf[ns][1],
                  sptr(&Wts[(n0 + ns * 8 + brow) * QSTRIDE + k0 + bcol]));
        #pragma unroll
        for (int ms = 0; ms < 4; ms++)
            #pragma unroll
            for (int ns = 0; ns < 4; ns++)
                mma16816(acc[ms][ns][0], acc[ms][ns][1], acc[ms][ns][2], acc[ms][ns][3],
                         A[ms][0], A[ms][1], A[ms][2], A[ms][3], Bf[ns][0], Bf[ns][1]);
    }

    #pragma unroll
    for (int ms = 0; ms < 4; ms++) {
        const int rA = m0 + ms * 16 + gid, rB = rA + 8;
        #pragma unroll
        for (int ns = 0; ns < 4; ns++) {
            const int c0 = n0 + ns * 8 + tid2 * 2;
            *(__nv_bfloat162*)&g_qt[(size_t)(r0 + rA) * DC + c0] =
                __floats2bfloat162_rn(acc[ms][ns][0], acc[ms][ns][1]);
            *(__nv_bfloat162*)&g_qt[(size_t)(r0 + rB) * DC + c0] =
                __floats2bfloat162_rn(acc[ms][ns][2], acc[ms][ns][3]);
        }
    }
    __syncthreads();
    if (t < 128) g_qsq[r0 + t] = qsq[t];
}

// ---------------- kernel 3: dequant codes + k_sq = kc^T G kc ----------------
#define PSTRIDE 136
#define SMEM_PREPK (2 * 128 * PSTRIDE * 2 + 512)

__global__ void k_prepk(const int* __restrict__ kq,
                        const float* __restrict__ kscale,
                        const float* __restrict__ kzero) {
    extern __shared__ char sm[];
    __nv_bfloat16* kcs  = (__nv_bfloat16*)sm;
    __nv_bfloat16* Gs   = kcs + 128 * PSTRIDE;
    float*         ksqs = (float*)(Gs + 128 * PSTRIDE);

    const int t    = threadIdx.x;
    const int row0 = blockIdx.x * 128;
    const int b    = row0 / LK;

    {
        const int c4 = (t & 31) * 4;
        const float4 sc = *(const float4*)(kscale + b * DC + c4);
        const float4 zr = *(const float4*)(kzero + b * DC + c4);
        const int rb = t >> 5;
        #pragma unroll
        for (int i = 0; i < 16; i++) {
            const int r = rb + i * 8;
            const int4 code = *(const int4*)(kq + (size_t)(row0 + r) * DC + c4);
            __nv_bfloat162 p0, p1;
            p0.x = __float2bfloat16(sc.x * ((float)code.x - zr.x));
            p0.y = __float2bfloat16(sc.y * ((float)code.y - zr.y));
            p1.x = __float2bfloat16(sc.z * ((float)code.z - zr.z));
            p1.y = __float2bfloat16(sc.w * ((float)code.w - zr.w));
            *(__nv_bfloat162*)&kcs[r * PSTRIDE + c4]     = p0;
            *(__nv_bfloat162*)&kcs[r * PSTRIDE + c4 + 2] = p1;
            *(__nv_bfloat162*)&g_kc[(size_t)(row0 + r) * DC + c4]     = p0;
            *(__nv_bfloat162*)&g_kc[(size_t)(row0 + r) * DC + c4 + 2] = p1;
        }
    }
    {
        const int r = t >> 1, ch = (t & 1) * 64;
        const uint4* src = (const uint4*)(g_G + r * DC + ch);
        #pragma unroll
        for (int i = 0; i < 8; i++) *(uint4*)&Gs[r * PSTRIDE + ch + i * 8] = src[i];
    }
    if (t < 128) ksqs[t] = 0.f;
    __syncthreads();

    const int w = t >> 5, lane = t & 31;
    const int m0 = (w >> 2) * 64, n0 = (w & 3) * 32;
    const int gid = lane >> 2, tid2 = lane & 3;
    const int arow = lane & 15, acol = ((lane >> 4) << 3);
    const int brow = lane & 7,  bcol = (((lane >> 3) & 1) << 3);

    float acc[4][4][4];
    #pragma unroll
    for (int i = 0; i < 4; i++)
        #pragma unroll
        for (int j = 0; j < 4; j++)
            #pragma unroll
            for (int c = 0; c < 4; c++) acc[i][j][c] = 0.f;

    #pragma unroll
    for (int ks = 0; ks < 8; ks++) {
        const int k0 = ks * 16;
        uint32_t A[4][4], Bf[4][2];
        #pragma unroll
        for (int ms = 0; ms < 4; ms++)
            ldsm4(A[ms][0], A[ms][1], A[ms][2], A[ms][3],
                  sptr(&kcs[(m0 + ms * 16 + arow) * PSTRIDE + k0 + acol]));
        #pragma unroll
        for (int ns = 0; ns < 4; ns++)
            ldsm2(Bf[ns][0], Bf[ns][1],
                  sptr(&Gs[(n0 + ns * 8 + brow) * PSTRIDE + k0 + bcol]));
        #pragma unroll
        for (int ms = 0; ms < 4; ms++)
            #pragma unroll
            for (int ns = 0; ns < 4; ns++)
                mma16816(acc[ms][ns][0], acc[ms][ns][1], acc[ms][ns][2], acc[ms][ns][3],
                         A[ms][0], A[ms][1], A[ms][2], A[ms][3], Bf[ns][0], Bf[ns][1]);
    }

    #pragma unroll
    for (int ms = 0; ms < 4; ms++) {
        const int rA = m0 + ms * 16 + gid, rB = rA + 8;
        float sA = 0.f, sB = 0.f;
        #pragma unroll
        for (int ns = 0; ns < 4; ns++) {
            const int c0 = n0 + ns * 8 + tid2 * 2;
            sA += acc[ms][ns][0] * __bfloat162float(kcs[rA * PSTRIDE + c0]);
            sA += acc[ms][ns][1] * __bfloat162float(kcs[rA * PSTRIDE + c0 + 1]);
            sB += acc[ms][ns][2] * __bfloat162float(kcs[rB * PSTRIDE + c0]);
            sB += acc[ms][ns][3] * __bfloat162float(kcs[rB * PSTRIDE + c0 + 1]);
        }
        atomicAdd(&ksqs[rA], sA);
        atomicAdd(&ksqs[rB], sB);
    }
    __syncthreads();
    if (t < 128) g_ksq[row0 + t] = ksqs[t];
}

// ---------------- kernel 4: main — 128x128 tile, permuted B cols, STG.128 ----------------
#define SMEM_MAIN (2 * 128 * PSTRIDE * 2 + 4 * 128 * 4 + 256)

__global__ void __launch_bounds__(256, 2) k_main(float* __restrict__ out) {
    extern __shared__ char sm[];
    __nv_bfloat16* qts  = (__nv_bfloat16*)sm;             // [128][136]
    __nv_bfloat16* kcs  = qts + 128 * PSTRIDE;            // [128][136] rows permuted
    float*         qsqs = (float*)(kcs + 128 * PSTRIDE);  // [128]
    float*         rqs  = qsqs + 128;                     // [128]
    float*         ksqs = rqs + 128;                      // [128] logical order
    float*         rks  = ksqs + 128;                     // [128] logical order

    const int t = threadIdx.x;                            // 256
    const int kb = blockIdx.x, qb = blockIdx.y, b = blockIdx.z;
    const int q0 = qb * 128, k0t = kb * 128;

    {
        const int r = t >> 1, ch = (t & 1) * 64;
        // permute k rows within each 16-group: logical l -> phys
        const int l = r & 15;
        const int pr = (r & ~15) | (((l >> 1) & 1) * 8 + ((l >> 2) << 1) + (l & 1));
        const uint4* s1 = (const uint4*)(g_qt + ((size_t)(b * LQ + q0 + r)) * DC + ch);
        const uint4* s2 = (const uint4*)(g_kc + ((size_t)(b * LK + k0t + r)) * DC + ch);
        #pragma unroll
        for (int i = 0; i < 8; i++) *(uint4*)&qts[r * PSTRIDE + ch + i * 8] = s1[i];
        #pragma unroll
        for (int i = 0; i < 8; i++) *(uint4*)&kcs[pr * PSTRIDE + ch + i * 8] = s2[i];
    }
    if (t < 128) {
        float qs = g_qsq[b * LQ + q0 + t];
        qsqs[t] = qs;
        rqs[t] = 1.f - fminf(qs, 1.f - EPSF);
    } else {
        int i = t - 128;
        float ks = g_ksq[b * LK + k0t + i];
        ksqs[i] = ks;
        rks[i] = 1.f - fminf(ks, 1.f - EPSF);
    }
    __syncthreads();

    const int w = t >> 5, lane = t & 31;
    const int m0 = (w >> 2) * 64, n0 = (w & 3) * 32;
    const int gid = lane >> 2, tid2 = lane & 3;
    const int arow = lane & 15, acol = ((lane >> 4) << 3);
    // B ldsm4 over 16 rows (two n8 tiles): lanes 0-7 rows 0-7 @k0, 8-15 rows 0-7 @k8,
    // 16-23 rows 8-15 @k0, 24-31 rows 8-15 @k8
    const int brow16 = (lane & 7) + ((lane >> 4) << 3);
    const int bcol16 = (((lane >> 3) & 1) << 3);

    float acc[4][4][4];
    #pragma unroll
    for (int i = 0; i < 4; i++)
        #pragma unroll
        for (int j = 0; j < 4; j++)
            #pragma unroll
            for (int c = 0; c < 4; c++) acc[i][j][c] = 0.f;

    #pragma unroll
    for (int ks = 0; ks < 8; ks++) {
        const int k0 = ks * 16;
        uint32_t A[4][4], Bf[2][4];
        #pragma unroll
        for (int ms = 0; ms < 4; ms++)
            ldsm4(A[ms][0], A[ms][1], A[ms][2], A[ms][3],
                  sptr(&qts[(m0 + ms * 16 + arow) * PSTRIDE + k0 + acol]));
        #pragma unroll
        for (int P = 0; P < 2; P++)
            ldsm4(Bf[P][0], Bf[P][1], Bf[P][2], Bf[P][3],
                  sptr(&kcs[(n0 + P * 16 + brow16) * PSTRIDE + k0 + bcol16]));
        #pragma unroll
        for (int ms = 0; ms < 4; ms++)
            #pragma unroll
            for (int P = 0; P < 2; P++) {
                mma16816(acc[ms][2*P][0], acc[ms][2*P][1], acc[ms][2*P][2], acc[ms][2*P][3],
                         A[ms][0], A[ms][1], A[ms][2], A[ms][3], Bf[P][0], Bf[P][1]);
                mma16816(acc[ms][2*P+1][0], acc[ms][2*P+1][1], acc[ms][2*P+1][2], acc[ms][2*P+1][3],
                         A[ms][0], A[ms][1], A[ms][2], A[ms][3], Bf[P][2], Bf[P][3]);
            }
    }

    // epilogue: thread owns 4 consecutive logical cols per tile-pair
    #pragma unroll
    for (int ms = 0; ms < 4; ms++) {
        const int rA = m0 + ms * 16 + gid, rB = rA + 8;
        const float qsA = qsqs[rA], qsB = qsqs[rB];
        const float rqA = rqs[rA],  rqB = rqs[rB];
        const size_t baseA = ((size_t)(b * LQ + q0 + rA)) * LK + k0t;
        const size_t baseB = baseA + (size_t)8 * LK;
        #pragma unroll
        for (int P = 0; P < 2; P++) {
            const int c0 = n0 + P * 16 + 4 * tid2;       // logical cols c0..c0+3
            const float4 ks4 = *(const float4*)&ksqs[c0];
            const float4 rk4 = *(const float4*)&rks[c0];
            // phys tile 2P gives logical cols c0,c0+1; tile 2P+1 gives c0+2,c0+3
            float vA[4] = { acc[ms][2*P][0], acc[ms][2*P][1], acc[ms][2*P+1][0], acc[ms][2*P+1][1] };
            float vB[4] = { acc[ms][2*P][2], acc[ms][2*P][3], acc[ms][2*P+1][2], acc[ms][2*P+1][3] };
            const float ksv[4] = { ks4.x, ks4.y, ks4.z, ks4.w };
            const float rkv[4] = { rk4.x, rk4.y, rk4.z, rk4.w };

            float dA[4], dB[4];
            bool bad = false;
            #pragma unroll
            for (int j = 0; j < 4; j++) {
                float uA = 2.f * fmaxf(fmaf(-2.f, vA[j], qsA + ksv[j]), 0.f);
                float nA = fmaf(rqA, rkv[j], EPSF);
                float uB = 2.f * fmaxf(fmaf(-2.f, vB[j], qsB + ksv[j]), 0.f);
                float nB = fmaf(rqB, rkv[j], EPSF);
                dA[j] = LN2F * (1.f + fast_lg2(uA + nA) - fast_lg2(nA));
                dB[j] = LN2F * (1.f + fast_lg2(uB + nB) - fast_lg2(nB));
                bad |= (uA < 100.f * nA) | (uB < 100.f * nB);
            }
            if (bad) {   // exact path (cold)
                #pragma unroll
                for (int j = 0; j < 4; j++) {
                    float uA = 2.f * fmaxf(fmaf(-2.f, vA[j], qsA + ksv[j]), 0.f);
                    float nA = fmaf(rqA, rkv[j], EPSF);
                    float tA = uA * fast_rcp(nA);
                    float sA = fast_sqrt(fmaf(tA, tA, 2.f * tA));
                    dA[j] = LN2F * fast_lg2(1.f + tA + sA);
                    float uB = 2.f * fmaxf(fmaf(-2.f, vB[j], qsB + ksv[j]), 0.f);
                    float nB = fmaf(rqB, rkv[j], EPSF);
                    float tB = uB * fast_rcp(nB);
                    float sB = fast_sqrt(fmaf(tB, tB, 2.f * tB));
                    dB[j] = LN2F * fast_lg2(1.f + tB + sB);
                }
            }
            __stcs((float4*)(out + baseA + c0), make_float4(dA[0], dA[1], dA[2], dA[3]));
            __stcs((float4*)(out + baseB + c0), make_float4(dB[0], dB[1], dB[2], dB[3]));
        }
    }
}

// ---------------- launch ----------------
extern "C" void kernel_launch(void* const* d_in, const int* in_sizes, int n_in,
                              void* d_out, int out_size) {
    const float* q   = (const float*)d_in[0];
    const int*   kq  = (const int*)d_in[1];
    const float* ksc = (const float*)d_in[2];
    const float* kz  = (const float*)d_in[3];
    const float* W   = (const float*)d_in[4];
    float* out = (float*)d_out;
    (void)in_sizes; (void)n_in; (void)out_size;

    cudaFuncSetAttribute(k_prepq, cudaFuncAttributeMaxDynamicSharedMemorySize, SMEM_PREPQ);
    cudaFuncSetAttribute(k_prepk, cudaFuncAttributeMaxDynamicSharedMemorySize, SMEM_PREPK);
    cudaFuncSetAttribute(k_main,  cudaFuncAttributeMaxDynamicSharedMemorySize, SMEM_MAIN);

    k_G<<<DC, 256>>>(W);
    k_prepq<<<(B_ * LQ) / 128, 256, SMEM_PREPQ>>>(q);
    k_prepk<<<(B_ * LK) / 128, 256, SMEM_PREPK>>>(kq, ksc, kz);
    k_main<<<dim3(LK / 128, LQ / 128, B_), 256, SMEM_MAIN>>>(out);
}

// round 7
// speedup vs baseline: 1.2717x; 1.0837x over previous
#include <cuda_runtime.h>
#include <cuda_bf16.h>
#include <cstdint>
#include <cmath>

#define B_   8
#define LQ   1024
#define LK   8192
#define D_   256
#define DC   128
#define EPSF 1e-6f
#define LN2F 0.69314718055994531f

// ---------------- scratch (no allocations allowed) ----------------
__device__ __nv_bfloat16  g_qt[B_ * LQ * DC];     // q~ = q @ W_up     (2 MB)
__device__ float          g_qsq[B_ * LQ];
__device__ __nv_bfloat16  g_kc[B_ * LK * DC];     // dequantized codes (16 MB)
__device__ float          g_ksq[B_ * LK];
__device__ __nv_bfloat16  g_G[DC * DC];           // G = W^T W (bf16)
__device__ __nv_bfloat16  g_Wt[DC * D_];          // W^T (c-major)

// ---------------- fast math ----------------
__device__ __forceinline__ float fast_rcp(float x)  { float r; asm("rcp.approx.f32 %0, %1;"  : "=f"(r) : "f"(x)); return r; }
__device__ __forceinline__ float fast_sqrt(float x) { float r; asm("sqrt.approx.f32 %0, %1;" : "=f"(r) : "f"(x)); return r; }
__device__ __forceinline__ float fast_lg2(float x)  { float r; asm("lg2.approx.f32 %0, %1;"  : "=f"(r) : "f"(x)); return r; }

// ---------------- mma helpers ----------------
__device__ __forceinline__ uint32_t sptr(const void* p) {
    return (uint32_t)__cvta_generic_to_shared(p);
}
__device__ __forceinline__ void ldsm4(uint32_t& a0, uint32_t& a1, uint32_t& a2, uint32_t& a3, uint32_t addr) {
    asm volatile("ldmatrix.sync.aligned.m8n8.x4.shared.b16 {%0,%1,%2,%3}, [%4];"
                 : "=r"(a0), "=r"(a1), "=r"(a2), "=r"(a3) : "r"(addr));
}
__device__ __forceinline__ void ldsm2(uint32_t& b0, uint32_t& b1, uint32_t addr) {
    asm volatile("ldmatrix.sync.aligned.m8n8.x2.shared.b16 {%0,%1}, [%2];"
                 : "=r"(b0), "=r"(b1) : "r"(addr));
}
__device__ __forceinline__ void mma16816(float& c0, float& c1, float& c2, float& c3,
                                         uint32_t a0, uint32_t a1, uint32_t a2, uint32_t a3,
                                         uint32_t b0, uint32_t b1) {
    asm volatile("mma.sync.aligned.m16n8k16.row.col.f32.bf16.bf16.f32 "
                 "{%0,%1,%2,%3}, {%4,%5,%6,%7}, {%8,%9}, {%0,%1,%2,%3};"
                 : "+f"(c0), "+f"(c1), "+f"(c2), "+f"(c3)
                 : "r"(a0), "r"(a1), "r"(a2), "r"(a3), "r"(b0), "r"(b1));
}
__device__ __forceinline__ void cp16(uint32_t dst, const void* src) {
    asm volatile("cp.async.cg.shared.global [%0], [%1], 16;" :: "r"(dst), "l"(src));
}
__device__ __forceinline__ void cp_commit() { asm volatile("cp.async.commit_group;" ::: "memory"); }
__device__ __forceinline__ void cp_wait0()  { asm volatile("cp.async.wait_group 0;" ::: "memory"); }

// ---------------- kernel 1: G = W^T W (bf16) + Wt bf16 ----------------
__global__ void k_G(const float* __restrict__ W) {
    __shared__ float col[D_];
    __shared__ float red[256];
    const int c1 = blockIdx.x;
    const int t  = threadIdx.x;
    const int c2 = t & 127, h = t >> 7;

    float wv = W[t * DC + c1];
    col[t] = wv;
    g_Wt[c1 * D_ + t] = __float2bfloat16(wv);
    __syncthreads();

    float acc = 0.f;
    const int d0 = h * 128;
    #pragma unroll 8
    for (int d = 0; d < 128; d++) acc += col[d0 + d] * W[(d0 + d) * DC + c2];
    red[t] = acc;
    __syncthreads();
    if (h == 0) g_G[c1 * DC + c2] = __float2bfloat16(red[c2] + red[c2 + 128]);
}

// ---------------- kernel 2: q~ = q @ W via MMA + q_sq ----------------
#define QSTRIDE 264
#define SMEM_PREPQ (128 * QSTRIDE * 2 * 2 + 256 * 4 + 128 * 4 + 256)

__global__ void k_prepq(const float* __restrict__ q) {
    extern __shared__ char sm[];
    __nv_bfloat16* qs  = (__nv_bfloat16*)sm;
    __nv_bfloat16* Wts = qs + 128 * QSTRIDE;
    float*         par = (float*)(Wts + 128 * QSTRIDE);
    float*         qsq = par + 256;

    const int t  = threadIdx.x;
    const int r0 = blockIdx.x * 128;

    {
        const float4* src = (const float4*)(q + (size_t)r0 * D_);
        #pragma unroll
        for (int i = 0; i < 32; i++) {
            int idx = t + i * 256;
            int row = idx >> 6, c4 = (idx & 63) * 4;
            float4 v = src[idx];
            *(__nv_bfloat162*)&qs[row * QSTRIDE + c4]     = __floats2bfloat162_rn(v.x, v.y);
            *(__nv_bfloat162*)&qs[row * QSTRIDE + c4 + 2] = __floats2bfloat162_rn(v.z, v.w);
        }
    }
    {
        const float4* rowp = (const float4*)(q + (size_t)(r0 + (t >> 1)) * D_) + (t & 1) * 32;
        float ss = 0.f;
        #pragma unroll 8
        for (int i = 0; i < 32; i++) {
            float4 v = rowp[i];
            ss += v.x * v.x + v.y * v.y + v.z * v.z + v.w * v.w;
        }
        par[t] = ss;
    }
    {
        #pragma unroll
        for (int i = 0; i < 16; i++) {
            int idx = t + i * 256;
            int r = idx >> 5, c8 = (idx & 31) * 8;
            *(uint4*)&Wts[r * QSTRIDE + c8] = ((const uint4*)g_Wt)[idx];
        }
    }
    __syncthreads();
    if (t < 128) qsq[t] = par[2 * t] + par[2 * t + 1];

    const int w = t >> 5, lane = t & 31;
    const int m0 = (w >> 2) * 64, n0 = (w & 3) * 32;
    const int gid = lane >> 2, tid2 = lane & 3;
    const int arow = lane & 15, acol = ((lane >> 4) << 3);
    const int brow = lane & 7,  bcol = (((lane >> 3) & 1) << 3);

    float acc[4][4][4];
    #pragma unroll
    for (int i = 0; i < 4; i++)
        #pragma unroll
        for (int j = 0; j < 4; j++)
            #pragma unroll
            for (int c = 0; c < 4; c++) acc[i][j][c] = 0.f;

    #pragma unroll
    for (int ks = 0; ks < 16; ks++) {
        const int k0 = ks * 16;
        uint32_t A[4][4], Bf[4][2];
        #pragma unroll
        for (int ms = 0; ms < 4; ms++)
            ldsm4(A[ms][0], A[ms][1], A[ms][2], A[ms][3],
                  sptr(&qs[(m0 + ms * 16 + arow) * QSTRIDE + k0 + acol]));
        #pragma unroll
        for (int ns = 0; ns < 4; ns++)
            ldsm2(Bf[ns][0], Bf[ns][1],
                  sptr(&Wts[(n0 + ns * 8 + brow) * QSTRIDE + k0 + bcol]));
        #pragma unroll
        for (int ms = 0; ms < 4; ms++)
            #pragma unroll
            for (int ns = 0; ns < 4; ns++)
                mma16816(acc[ms][ns][0], acc[ms][ns][1], acc[ms][ns][2], acc[ms][ns][3],
                         A[ms][0], A[ms][1], A[ms][2], A[ms][3], Bf[ns][0], Bf[ns][1]);
    }

    #pragma unroll
    for (int ms = 0; ms < 4; ms++) {
        const int rA = m0 + ms * 16 + gid, rB = rA + 8;
        #pragma unroll
        for (int ns = 0; ns < 4; ns++) {
            const int c0 = n0 + ns * 8 + tid2 * 2;
            *(__nv_bfloat162*)&g_qt[(size_t)(r0 + rA) * DC + c0] =
                __floats2bfloat162_rn(acc[ms][ns][0], acc[ms][ns][1]);
            *(__nv_bfloat162*)&g_qt[(size_t)(r0 + rB) * DC + c0] =
                __floats2bfloat162_rn(acc[ms][ns][2], acc[ms][ns][3]);
        }
    }
    __syncthreads();
    if (t < 128) g_qsq[r0 + t] = qsq[t];
}

// ---------------- kernel 3: dequant codes + k_sq = kc^T G kc ----------------
#define PSTRIDE 136
#define SMEM_PREPK (2 * 128 * PSTRIDE * 2 + 512)

__global__ void k_prepk(const int* __restrict__ kq,
                        const float* __restrict__ kscale,
                        const float* __restrict__ kzero) {
    extern __shared__ char sm[];
    __nv_bfloat16* kcs  = (__nv_bfloat16*)sm;
    __nv_bfloat16* Gs   = kcs + 128 * PSTRIDE;
    float*         ksqs = (float*)(Gs + 128 * PSTRIDE);

    const int t    = threadIdx.x;
    const int row0 = blockIdx.x * 128;
    const int b    = row0 / LK;

    {
        const int c4 = (t & 31) * 4;
        const float4 sc = *(const float4*)(kscale + b * DC + c4);
        const float4 zr = *(const float4*)(kzero + b * DC + c4);
        const int rb = t >> 5;
        #pragma unroll
        for (int i = 0; i < 16; i++) {
            const int r = rb + i * 8;
            const int4 code = *(const int4*)(kq + (size_t)(row0 + r) * DC + c4);
            __nv_bfloat162 p0, p1;
            p0.x = __float2bfloat16(sc.x * ((float)code.x - zr.x));
            p0.y = __float2bfloat16(sc.y * ((float)code.y - zr.y));
            p1.x = __float2bfloat16(sc.z * ((float)code.z - zr.z));
            p1.y = __float2bfloat16(sc.w * ((float)code.w - zr.w));
            *(__nv_bfloat162*)&kcs[r * PSTRIDE + c4]     = p0;
            *(__nv_bfloat162*)&kcs[r * PSTRIDE + c4 + 2] = p1;
            *(__nv_bfloat162*)&g_kc[(size_t)(row0 + r) * DC + c4]     = p0;
            *(__nv_bfloat162*)&g_kc[(size_t)(row0 + r) * DC + c4 + 2] = p1;
        }
    }
    {
        const int r = t >> 1, ch = (t & 1) * 64;
        const uint4* src = (const uint4*)(g_G + r * DC + ch);
        #pragma unroll
        for (int i = 0; i < 8; i++) *(uint4*)&Gs[r * PSTRIDE + ch + i * 8] = src[i];
    }
    if (t < 128) ksqs[t] = 0.f;
    __syncthreads();

    const int w = t >> 5, lane = t & 31;
    const int m0 = (w >> 2) * 64, n0 = (w & 3) * 32;
    const int gid = lane >> 2, tid2 = lane & 3;
    const int arow = lane & 15, acol = ((lane >> 4) << 3);
    const int brow = lane & 7,  bcol = (((lane >> 3) & 1) << 3);

    float acc[4][4][4];
    #pragma unroll
    for (int i = 0; i < 4; i++)
        #pragma unroll
        for (int j = 0; j < 4; j++)
            #pragma unroll
            for (int c = 0; c < 4; c++) acc[i][j][c] = 0.f;

    #pragma unroll
    for (int ks = 0; ks < 8; ks++) {
        const int k0 = ks * 16;
        uint32_t A[4][4], Bf[4][2];
        #pragma unroll
        for (int ms = 0; ms < 4; ms++)
            ldsm4(A[ms][0], A[ms][1], A[ms][2], A[ms][3],
                  sptr(&kcs[(m0 + ms * 16 + arow) * PSTRIDE + k0 + acol]));
        #pragma unroll
        for (int ns = 0; ns < 4; ns++)
            ldsm2(Bf[ns][0], Bf[ns][1],
                  sptr(&Gs[(n0 + ns * 8 + brow) * PSTRIDE + k0 + bcol]));
        #pragma unroll
        for (int ms = 0; ms < 4; ms++)
            #pragma unroll
            for (int ns = 0; ns < 4; ns++)
                mma16816(acc[ms][ns][0], acc[ms][ns][1], acc[ms][ns][2], acc[ms][ns][3],
                         A[ms][0], A[ms][1], A[ms][2], A[ms][3], Bf[ns][0], Bf[ns][1]);
    }

    #pragma unroll
    for (int ms = 0; ms < 4; ms++) {
        const int rA = m0 + ms * 16 + gid, rB = rA + 8;
        float sA = 0.f, sB = 0.f;
        #pragma unroll
        for (int ns = 0; ns < 4; ns++) {
            const int c0 = n0 + ns * 8 + tid2 * 2;
            sA += acc[ms][ns][0] * __bfloat162float(kcs[rA * PSTRIDE + c0]);
            sA += acc[ms][ns][1] * __bfloat162float(kcs[rA * PSTRIDE + c0 + 1]);
            sB += acc[ms][ns][2] * __bfloat162float(kcs[rB * PSTRIDE + c0]);
            sB += acc[ms][ns][3] * __bfloat162float(kcs[rB * PSTRIDE + c0 + 1]);
        }
        atomicAdd(&ksqs[rA], sA);
        atomicAdd(&ksqs[rB], sB);
    }
    __syncthreads();
    if (t < 128) g_ksq[row0 + t] = ksqs[t];
}

// ---------------- kernel 4: main — KB-loop + cp.async double buffer ----------------
#define KB 4
#define SMEM_MAIN (128 * PSTRIDE * 2 + 2 * 128 * PSTRIDE * 2 + 2 * 128 * 4 + 2 * 128 * 4 + 256)

__global__ void __launch_bounds__(256, 2) k_main(float* __restrict__ out) {
    extern __shared__ char sm[];
    __nv_bfloat16* qts  = (__nv_bfloat16*)sm;                 // [128][136]
    __nv_bfloat16* kcs  = qts + 128 * PSTRIDE;                // [2][128][136] dbl-buffered, rows permuted
    float*         qsqs = (float*)(kcs + 2 * 128 * PSTRIDE);  // [128]
    float*         rqs  = qsqs + 128;                         // [128]
    float*         ksqr = rqs + 128;                          // [2][128] raw ksq

    const int t = threadIdx.x;                                // 256
    const int kbb = blockIdx.x, qb = blockIdx.y, b = blockIdx.z;
    const int q0 = qb * 128, kbase = kbb * (128 * KB);

    const int r  = t >> 1, ch = (t & 1) * 64;
    const int l  = r & 15;
    const int pr = (r & ~15) | (((l >> 1) & 1) * 8 + ((l >> 2) << 1) + (l & 1));

    // q tile (once)
    {
        const uint4* s1 = (const uint4*)(g_qt + ((size_t)(b * LQ + q0 + r)) * DC + ch);
        #pragma unroll
        for (int i = 0; i < 8; i++) *(uint4*)&qts[r * PSTRIDE + ch + i * 8] = s1[i];
    }
    if (t < 128) {
        float qs = g_qsq[b * LQ + q0 + t];
        qsqs[t] = qs;
        rqs[t] = 1.f - fminf(qs, 1.f - EPSF);
    }

    // prefetch k buffer 0
    {
        const uint32_t dst = sptr(&kcs[pr * PSTRIDE + ch]);
        const char* src = (const char*)(g_kc + ((size_t)(b * LK + kbase + r)) * DC + ch);
        #pragma unroll
        for (int i = 0; i < 8; i++) cp16(dst + i * 16, src + i * 16);
        if (t < 32) cp16(sptr(&ksqr[t * 4]), g_ksq + b * LK + kbase + t * 4);
    }
    cp_commit();

    const int w = t >> 5, lane = t & 31;
    const int m0 = (w >> 2) * 64, n0 = (w & 3) * 32;
    const int gid = lane >> 2, tid2 = lane & 3;
    const int arow = lane & 15, acol = ((lane >> 4) << 3);
    const int brow16 = (lane & 7) + ((lane >> 4) << 3);
    const int bcol16 = (((lane >> 3) & 1) << 3);

    for (int kb = 0; kb < KB; kb++) {
        cp_wait0();
        __syncthreads();

        // prefetch next k buffer while computing this one
        if (kb + 1 < KB) {
            const int nb = (kb + 1) & 1;
            const uint32_t dst = sptr(&kcs[nb * 128 * PSTRIDE + pr * PSTRIDE + ch]);
            const char* src = (const char*)(g_kc + ((size_t)(b * LK + kbase + (kb + 1) * 128 + r)) * DC + ch);
            #pragma unroll
            for (int i = 0; i < 8; i++) cp16(dst + i * 16, src + i * 16);
            if (t < 32) cp16(sptr(&ksqr[nb * 128 + t * 4]),
                             g_ksq + b * LK + kbase + (kb + 1) * 128 + t * 4);
            cp_commit();
        }

        const __nv_bfloat16* kbuf = kcs + (kb & 1) * 128 * PSTRIDE;
        const float*         kraw = ksqr + (kb & 1) * 128;
        const int k0t = kbase + kb * 128;

        float acc[4][4][4];
        #pragma unroll
        for (int i = 0; i < 4; i++)
            #pragma unroll
            for (int j = 0; j < 4; j++)
                #pragma unroll
                for (int c = 0; c < 4; c++) acc[i][j][c] = 0.f;

        #pragma unroll
        for (int ks = 0; ks < 8; ks++) {
            const int k0 = ks * 16;
            uint32_t A[4][4], Bf[2][4];
            #pragma unroll
            for (int ms = 0; ms < 4; ms++)
                ldsm4(A[ms][0], A[ms][1], A[ms][2], A[ms][3],
                      sptr(&qts[(m0 + ms * 16 + arow) * PSTRIDE + k0 + acol]));
            #pragma unroll
            for (int P = 0; P < 2; P++)
                ldsm4(Bf[P][0], Bf[P][1], Bf[P][2], Bf[P][3],
                      sptr(&kbuf[(n0 + P * 16 + brow16) * PSTRIDE + k0 + bcol16]));
            #pragma unroll
            for (int ms = 0; ms < 4; ms++)
                #pragma unroll
                for (int P = 0; P < 2; P++) {
                    mma16816(acc[ms][2*P][0], acc[ms][2*P][1], acc[ms][2*P][2], acc[ms][2*P][3],
                             A[ms][0], A[ms][1], A[ms][2], A[ms][3], Bf[P][0], Bf[P][1]);
                    mma16816(acc[ms][2*P+1][0], acc[ms][2*P+1][1], acc[ms][2*P+1][2], acc[ms][2*P+1][3],
                             A[ms][0], A[ms][1], A[ms][2], A[ms][3], Bf[P][2], Bf[P][3]);
                }
        }

        // epilogue: thread owns 4 consecutive logical cols per tile-pair
        #pragma unroll
        for (int ms = 0; ms < 4; ms++) {
            const int rA = m0 + ms * 16 + gid, rB = rA + 8;
            const float qsA = qsqs[rA], qsB = qsqs[rB];
            const float rqA = rqs[rA],  rqB = rqs[rB];
            const size_t baseA = ((size_t)(b * LQ + q0 + rA)) * LK + k0t;
            const size_t baseB = baseA + (size_t)8 * LK;
            #pragma unroll
            for (int P = 0; P < 2; P++) {
                const int c0 = n0 + P * 16 + 4 * tid2;
                const float4 ks4 = *(const float4*)&kraw[c0];
                float vA[4] = { acc[ms][2*P][0], acc[ms][2*P][1], acc[ms][2*P+1][0], acc[ms][2*P+1][1] };
                float vB[4] = { acc[ms][2*P][2], acc[ms][2*P][3], acc[ms][2*P+1][2], acc[ms][2*P+1][3] };
                const float ksv[4] = { ks4.x, ks4.y, ks4.z, ks4.w };

                float dA[4], dB[4];
                bool bad = false;
                #pragma unroll
                for (int j = 0; j < 4; j++) {
                    const float rkj = 1.f - fminf(ksv[j], 1.f - EPSF);
                    float uA = 2.f * fmaxf(fmaf(-2.f, vA[j], qsA + ksv[j]), 0.f);
                    float nA = fmaf(rqA, rkj, EPSF);
                    float uB = 2.f * fmaxf(fmaf(-2.f, vB[j], qsB + ksv[j]), 0.f);
                    float nB = fmaf(rqB, rkj, EPSF);
                    dA[j] = LN2F * (1.f + fast_lg2(uA + nA) - fast_lg2(nA));
                    dB[j] = LN2F * (1.f + fast_lg2(uB + nB) - fast_lg2(nB));
                    bad |= (uA < 100.f * nA) | (uB < 100.f * nB);
                }
                if (bad) {   // exact path (cold)
                    #pragma unroll
                    for (int j = 0; j < 4; j++) {
                        const float rkj = 1.f - fminf(ksv[j], 1.f - EPSF);
                        float uA = 2.f * fmaxf(fmaf(-2.f, vA[j], qsA + ksv[j]), 0.f);
                        float nA = fmaf(rqA, rkj, EPSF);
                        float tA = uA * fast_rcp(nA);
                        float sA = fast_sqrt(fmaf(tA, tA, 2.f * tA));
                        dA[j] = LN2F * fast_lg2(1.f + tA + sA);
                        float uB = 2.f * fmaxf(fmaf(-2.f, vB[j], qsB + ksv[j]), 0.f);
                        float nB = fmaf(rqB, rkj, EPSF);
                        float tB = uB * fast_rcp(nB);
                        float sB = fast_sqrt(fmaf(tB, tB, 2.f * tB));
                        dB[j] = LN2F * fast_lg2(1.f + tB + sB);
                    }
                }
                __stcs((float4*)(out + baseA + c0), make_float4(dA[0], dA[1], dA[2], dA[3]));
                __stcs((float4*)(out + baseB + c0), make_float4(dB[0], dB[1], dB[2], dB[3]));
            }
        }
        __syncthreads();
    }
}

// ---------------- launch ----------------
extern "C" void kernel_launch(void* const* d_in, const int* in_sizes, int n_in,
                              void* d_out, int out_size) {
    const float* q   = (const float*)d_in[0];
    const int*   kq  = (const int*)d_in[1];
    const float* ksc = (const float*)d_in[2];
    const float* kz  = (const float*)d_in[3];
    const float* W   = (const float*)d_in[4];
    float* out = (float*)d_out;
    (void)in_sizes; (void)n_in; (void)out_size;

    cudaFuncSetAttribute(k_prepq, cudaFuncAttributeMaxDynamicSharedMemorySize, SMEM_PREPQ);
    cudaFuncSetAttribute(k_prepk, cudaFuncAttributeMaxDynamicSharedMemorySize, SMEM_PREPK);
    cudaFuncSetAttribute(k_main,  cudaFuncAttributeMaxDynamicSharedMemorySize, SMEM_MAIN);

    k_G<<<DC, 256>>>(W);
    k_prepq<<<(B_ * LQ) / 128, 256, SMEM_PREPQ>>>(q);
    k_prepk<<<(B_ * LK) / 128, 256, SMEM_PREPK>>>(kq, ksc, kz);
    k_main<<<dim3(LK / (128 * KB), LQ / 128, B_), 256, SMEM_MAIN>>>(out);
}

// round 8
// speedup vs baseline: 1.3661x; 1.0742x over previous
#include <cuda_runtime.h>
#include <cuda_bf16.h>
#include <cstdint>
#include <cmath>

#define B_   8
#define LQ   1024
#define LK   8192
#define D_   256
#define DC   128
#define EPSF 1e-6f
#define LN2F 0.69314718055994531f

// ---------------- scratch (no allocations allowed) ----------------
__device__ uint8_t        g_qt8[B_ * LQ * DC];    // q~ = q @ W_up, e4m3 (1 MB)
__device__ float          g_qsq[B_ * LQ];
__device__ uint8_t        g_kc8[B_ * LK * DC];    // dequantized codes, e4m3 (8 MB)
__device__ float          g_ksq[B_ * LK];
__device__ __nv_bfloat16  g_G[DC * DC];           // G = W^T W (bf16)
__device__ __nv_bfloat16  g_Wt[DC * D_];          // W^T (c-major)

// ---------------- fast math ----------------
__device__ __forceinline__ float fast_rcp(float x)  { float r; asm("rcp.approx.f32 %0, %1;"  : "=f"(r) : "f"(x)); return r; }
__device__ __forceinline__ float fast_sqrt(float x) { float r; asm("sqrt.approx.f32 %0, %1;" : "=f"(r) : "f"(x)); return r; }
__device__ __forceinline__ float fast_lg2(float x)  { float r; asm("lg2.approx.f32 %0, %1;"  : "=f"(r) : "f"(x)); return r; }
// pack two f32 -> e4m3x2 (byte0 = lo, byte1 = hi)
__device__ __forceinline__ uint16_t pack_e4m3x2(float lo, float hi) {
    uint16_t u;
    asm("cvt.rn.satfinite.e4m3x2.f32 %0, %1, %2;" : "=h"(u) : "f"(hi), "f"(lo));
    return u;
}

// ---------------- mma helpers ----------------
__device__ __forceinline__ uint32_t sptr(const void* p) {
    return (uint32_t)__cvta_generic_to_shared(p);
}
__device__ __forceinline__ void ldsm4(uint32_t& a0, uint32_t& a1, uint32_t& a2, uint32_t& a3, uint32_t addr) {
    asm volatile("ldmatrix.sync.aligned.m8n8.x4.shared.b16 {%0,%1,%2,%3}, [%4];"
                 : "=r"(a0), "=r"(a1), "=r"(a2), "=r"(a3) : "r"(addr));
}
__device__ __forceinline__ void ldsm2(uint32_t& b0, uint32_t& b1, uint32_t addr) {
    asm volatile("ldmatrix.sync.aligned.m8n8.x2.shared.b16 {%0,%1}, [%2];"
                 : "=r"(b0), "=r"(b1) : "r"(addr));
}
__device__ __forceinline__ void mma16816(float& c0, float& c1, float& c2, float& c3,
                                         uint32_t a0, uint32_t a1, uint32_t a2, uint32_t a3,
                                         uint32_t b0, uint32_t b1) {
    asm volatile("mma.sync.aligned.m16n8k16.row.col.f32.bf16.bf16.f32 "
                 "{%0,%1,%2,%3}, {%4,%5,%6,%7}, {%8,%9}, {%0,%1,%2,%3};"
                 : "+f"(c0), "+f"(c1), "+f"(c2), "+f"(c3)
                 : "r"(a0), "r"(a1), "r"(a2), "r"(a3), "r"(b0), "r"(b1));
}
__device__ __forceinline__ void mma16832fp8(float& c0, float& c1, float& c2, float& c3,
                                            uint32_t a0, uint32_t a1, uint32_t a2, uint32_t a3,
                                            uint32_t b0, uint32_t b1) {
    asm volatile("mma.sync.aligned.m16n8k32.row.col.f32.e4m3.e4m3.f32 "
                 "{%0,%1,%2,%3}, {%4,%5,%6,%7}, {%8,%9}, {%0,%1,%2,%3};"
                 : "+f"(c0), "+f"(c1), "+f"(c2), "+f"(c3)
                 : "r"(a0), "r"(a1), "r"(a2), "r"(a3), "r"(b0), "r"(b1));
}
__device__ __forceinline__ void cp16(uint32_t dst, const void* src) {
    asm volatile("cp.async.cg.shared.global [%0], [%1], 16;" :: "r"(dst), "l"(src));
}
__device__ __forceinline__ void cp_commit() { asm volatile("cp.async.commit_group;" ::: "memory"); }
__device__ __forceinline__ void cp_wait0()  { asm volatile("cp.async.wait_group 0;" ::: "memory"); }

// ---------------- kernel 1: G = W^T W (bf16) + Wt bf16 ----------------
__global__ void k_G(const float* __restrict__ W) {
    __shared__ float col[D_];
    __shared__ float red[256];
    const int c1 = blockIdx.x;
    const int t  = threadIdx.x;
    const int c2 = t & 127, h = t >> 7;

    float wv = W[t * DC + c1];
    col[t] = wv;
    g_Wt[c1 * D_ + t] = __float2bfloat16(wv);
    __syncthreads();

    float acc = 0.f;
    const int d0 = h * 128;
    #pragma unroll 8
    for (int d = 0; d < 128; d++) acc += col[d0 + d] * W[(d0 + d) * DC + c2];
    red[t] = acc;
    __syncthreads();
    if (h == 0) g_G[c1 * DC + c2] = __float2bfloat16(red[c2] + red[c2 + 128]);
}

// ---------------- kernel 2: q~ = q @ W via MMA + q_sq (outputs e4m3) ----------------
#define QSTRIDE 264
#define SMEM_PREPQ (128 * QSTRIDE * 2 * 2 + 256 * 4 + 128 * 4 + 256)

__global__ void k_prepq(const float* __restrict__ q) {
    extern __shared__ char sm[];
    __nv_bfloat16* qs  = (__nv_bfloat16*)sm;
    __nv_bfloat16* Wts = qs + 128 * QSTRIDE;
    float*         par = (float*)(Wts + 128 * QSTRIDE);
    float*         qsq = par + 256;

    const int t  = threadIdx.x;
    const int r0 = blockIdx.x * 128;

    {
        const float4* src = (const float4*)(q + (size_t)r0 * D_);
        #pragma unroll
        for (int i = 0; i < 32; i++) {
            int idx = t + i * 256;
            int row = idx >> 6, c4 = (idx & 63) * 4;
            float4 v = src[idx];
            *(__nv_bfloat162*)&qs[row * QSTRIDE + c4]     = __floats2bfloat162_rn(v.x, v.y);
            *(__nv_bfloat162*)&qs[row * QSTRIDE + c4 + 2] = __floats2bfloat162_rn(v.z, v.w);
        }
    }
    {
        const float4* rowp = (const float4*)(q + (size_t)(r0 + (t >> 1)) * D_) + (t & 1) * 32;
        float ss = 0.f;
        #pragma unroll 8
        for (int i = 0; i < 32; i++) {
            float4 v = rowp[i];
            ss += v.x * v.x + v.y * v.y + v.z * v.z + v.w * v.w;
        }
        par[t] = ss;
    }
    {
        #pragma unroll
        for (int i = 0; i < 16; i++) {
            int idx = t + i * 256;
            int r = idx >> 5, c8 = (idx & 31) * 8;
            *(uint4*)&Wts[r * QSTRIDE + c8] = ((const uint4*)g_Wt)[idx];
        }
    }
    __syncthreads();
    if (t < 128) qsq[t] = par[2 * t] + par[2 * t + 1];

    const int w = t >> 5, lane = t & 31;
    const int m0 = (w >> 2) * 64, n0 = (w & 3) * 32;
    const int gid = lane >> 2, tid2 = lane & 3;
    const int arow = lane & 15, acol = ((lane >> 4) << 3);
    const int brow = lane & 7,  bcol = (((lane >> 3) & 1) << 3);

    float acc[4][4][4];
    #pragma unroll
    for (int i = 0; i < 4; i++)
        #pragma unroll
        for (int j = 0; j < 4; j++)
            #pragma unroll
            for (int c = 0; c < 4; c++) acc[i][j][c] = 0.f;

    #pragma unroll
    for (int ks = 0; ks < 16; ks++) {
        const int k0 = ks * 16;
        uint32_t A[4][4], Bf[4][2];
        #pragma unroll
        for (int ms = 0; ms < 4; ms++)
            ldsm4(A[ms][0], A[ms][1], A[ms][2], A[ms][3],
                  sptr(&qs[(m0 + ms * 16 + arow) * QSTRIDE + k0 + acol]));
        #pragma unroll
        for (int ns = 0; ns < 4; ns++)
            ldsm2(Bf[ns][0], Bf[ns][1],
                  sptr(&Wts[(n0 + ns * 8 + brow) * QSTRIDE + k0 + bcol]));
        #pragma unroll
        for (int ms = 0; ms < 4; ms++)
            #pragma unroll
            for (int ns = 0; ns < 4; ns++)
                mma16816(acc[ms][ns][0], acc[ms][ns][1], acc[ms][ns][2], acc[ms][ns][3],
                         A[ms][0], A[ms][1], A[ms][2], A[ms][3], Bf[ns][0], Bf[ns][1]);
    }

    #pragma unroll
    for (int ms = 0; ms < 4; ms++) {
        const int rA = m0 + ms * 16 + gid, rB = rA + 8;
        #pragma unroll
        for (int ns = 0; ns < 4; ns++) {
            const int c0 = n0 + ns * 8 + tid2 * 2;
            *(uint16_t*)&g_qt8[(size_t)(r0 + rA) * DC + c0] = pack_e4m3x2(acc[ms][ns][0], acc[ms][ns][1]);
            *(uint16_t*)&g_qt8[(size_t)(r0 + rB) * DC + c0] = pack_e4m3x2(acc[ms][ns][2], acc[ms][ns][3]);
        }
    }
    __syncthreads();
    if (t < 128) g_qsq[r0 + t] = qsq[t];
}

// ---------------- kernel 3: dequant codes + k_sq = kc^T G kc (outputs e4m3) ----------------
#define PSTRIDE 136
#define SMEM_PREPK (2 * 128 * PSTRIDE * 2 + 512)

__global__ void k_prepk(const int* __restrict__ kq,
                        const float* __restrict__ kscale,
                        const float* __restrict__ kzero) {
    extern __shared__ char sm[];
    __nv_bfloat16* kcs  = (__nv_bfloat16*)sm;
    __nv_bfloat16* Gs   = kcs + 128 * PSTRIDE;
    float*         ksqs = (float*)(Gs + 128 * PSTRIDE);

    const int t    = threadIdx.x;
    const int row0 = blockIdx.x * 128;
    const int b    = row0 / LK;

    {
        const int c4 = (t & 31) * 4;
        const float4 sc = *(const float4*)(kscale + b * DC + c4);
        const float4 zr = *(const float4*)(kzero + b * DC + c4);
        const int rb = t >> 5;
        #pragma unroll
        for (int i = 0; i < 16; i++) {
            const int r = rb + i * 8;
            const int4 code = *(const int4*)(kq + (size_t)(row0 + r) * DC + c4);
            float v0 = sc.x * ((float)code.x - zr.x);
            float v1 = sc.y * ((float)code.y - zr.y);
            float v2 = sc.z * ((float)code.z - zr.z);
            float v3 = sc.w * ((float)code.w - zr.w);
            __nv_bfloat162 p0, p1;
            p0.x = __float2bfloat16(v0); p0.y = __float2bfloat16(v1);
            p1.x = __float2bfloat16(v2); p1.y = __float2bfloat16(v3);
            *(__nv_bfloat162*)&kcs[r * PSTRIDE + c4]     = p0;
            *(__nv_bfloat162*)&kcs[r * PSTRIDE + c4 + 2] = p1;
            uint32_t pk = (uint32_t)pack_e4m3x2(v0, v1) | ((uint32_t)pack_e4m3x2(v2, v3) << 16);
            *(uint32_t*)&g_kc8[(size_t)(row0 + r) * DC + c4] = pk;
        }
    }
    {
        const int r = t >> 1, ch = (t & 1) * 64;
        const uint4* src = (const uint4*)(g_G + r * DC + ch);
        #pragma unroll
        for (int i = 0; i < 8; i++) *(uint4*)&Gs[r * PSTRIDE + ch + i * 8] = src[i];
    }
    if (t < 128) ksqs[t] = 0.f;
    __syncthreads();

    const int w = t >> 5, lane = t & 31;
    const int m0 = (w >> 2) * 64, n0 = (w & 3) * 32;
    const int gid = lane >> 2, tid2 = lane & 3;
    const int arow = lane & 15, acol = ((lane >> 4) << 3);
    const int brow = lane & 7,  bcol = (((lane >> 3) & 1) << 3);

    float acc[4][4][4];
    #pragma unroll
    for (int i = 0; i < 4; i++)
        #pragma unroll
        for (int j = 0; j < 4; j++)
            #pragma unroll
            for (int c = 0; c < 4; c++) acc[i][j][c] = 0.f;

    #pragma unroll
    for (int ks = 0; ks < 8; ks++) {
        const int k0 = ks * 16;
        uint32_t A[4][4], Bf[4][2];
        #pragma unroll
        for (int ms = 0; ms < 4; ms++)
            ldsm4(A[ms][0], A[ms][1], A[ms][2], A[ms][3],
                  sptr(&kcs[(m0 + ms * 16 + arow) * PSTRIDE + k0 + acol]));
        #pragma unroll
        for (int ns = 0; ns < 4; ns++)
            ldsm2(Bf[ns][0], Bf[ns][1],
                  sptr(&Gs[(n0 + ns * 8 + brow) * PSTRIDE + k0 + bcol]));
        #pragma unroll
        for (int ms = 0; ms < 4; ms++)
            #pragma unroll
            for (int ns = 0; ns < 4; ns++)
                mma16816(acc[ms][ns][0], acc[ms][ns][1], acc[ms][ns][2], acc[ms][ns][3],
                         A[ms][0], A[ms][1], A[ms][2], A[ms][3], Bf[ns][0], Bf[ns][1]);
    }

    #pragma unroll
    for (int ms = 0; ms < 4; ms++) {
        const int rA = m0 + ms * 16 + gid, rB = rA + 8;
        float sA = 0.f, sB = 0.f;
        #pragma unroll
        for (int ns = 0; ns < 4; ns++) {
            const int c0 = n0 + ns * 8 + tid2 * 2;
            sA += acc[ms][ns][0] * __bfloat162float(kcs[rA * PSTRIDE + c0]);
            sA += acc[ms][ns][1] * __bfloat162float(kcs[rA * PSTRIDE + c0 + 1]);
            sB += acc[ms][ns][2] * __bfloat162float(kcs[rB * PSTRIDE + c0]);
            sB += acc[ms][ns][3] * __bfloat162float(kcs[rB * PSTRIDE + c0 + 1]);
        }
        atomicAdd(&ksqs[rA], sA);
        atomicAdd(&ksqs[rB], sB);
    }
    __syncthreads();
    if (t < 128) g_ksq[row0 + t] = ksqs[t];
}

// ---------------- kernel 4: main — FP8 MMA, KB-loop + cp.async double buffer ----------------
#define KB 2
#define PS8 144                      // bytes per 128-byte row (16B skew)
#define QT8_BYTES (128 * PS8)        // 18432
#define SM_KT8    QT8_BYTES
#define SM_NRM    (QT8_BYTES * 3)    // 55296
#define SMEM_MAIN (QT8_BYTES * 3 + 4 * 128 * 4 + 256)

__global__ void __launch_bounds__(256, 2) k_main(float* __restrict__ out) {
    extern __shared__ char sm[];
    uint8_t* qts  = (uint8_t*)sm;                      // [128][144] e4m3
    uint8_t* kcs  = (uint8_t*)sm + SM_KT8;             // [2][128][144] e4m3, rows permuted
    float*   qsqs = (float*)(sm + SM_NRM);             // [128]
    float*   rqs  = qsqs + 128;                        // [128]
    float*   ksqr = rqs + 128;                         // [2][128]

    const int t = threadIdx.x;                         // 256
    const int kbb = blockIdx.x, qb = blockIdx.y, b = blockIdx.z;
    const int q0 = qb * 128, kbase = kbb * (128 * KB);

    const int r  = t >> 1, chb = (t & 1) * 64;         // byte offset half
    const int l  = r & 15;
    const int pr = (r & ~15) | (((l >> 1) & 1) * 8 + ((l >> 2) << 1) + (l & 1));

    // q tile (once): 128 rows x 128B
    {
        const uint4* s1 = (const uint4*)(g_qt8 + ((size_t)(b * LQ + q0 + r)) * DC + chb);
        #pragma unroll
        for (int i = 0; i < 4; i++) *(uint4*)(qts + r * PS8 + chb + i * 16) = s1[i];
    }
    if (t < 128) {
        float qs = g_qsq[b * LQ + q0 + t];
        qsqs[t] = qs;
        rqs[t] = 1.f - fminf(qs, 1.f - EPSF);
    }

    // prefetch k buffer 0
    {
        const uint32_t dst = sptr(kcs + pr * PS8 + chb);
        const char* src = (const char*)(g_kc8 + ((size_t)(b * LK + kbase + r)) * DC + chb);
        #pragma unroll
        for (int i = 0; i < 4; i++) cp16(dst + i * 16, src + i * 16);
        if (t < 32) cp16(sptr(&ksqr[t * 4]), g_ksq + b * LK + kbase + t * 4);
    }
    cp_commit();

    const int w = t >> 5, lane = t & 31;
    const int m0 = (w >> 2) * 64, n0 = (w & 3) * 32;
    const int gid = lane >> 2, tid2 = lane & 3;
    const int arow = lane & 15, acolb = ((lane >> 4) << 4);           // byte offset
    const int brow16 = (lane & 7) + ((lane >> 4) << 3);
    const int bcolb = (((lane >> 3) & 1) << 4);                       // byte offset

    for (int kb = 0; kb < KB; kb++) {
        cp_wait0();
        __syncthreads();

        if (kb + 1 < KB) {
            const int nb = (kb + 1) & 1;
            const uint32_t dst = sptr(kcs + nb * QT8_BYTES + pr * PS8 + chb);
            const char* src = (const char*)(g_kc8 + ((size_t)(b * LK + kbase + (kb + 1) * 128 + r)) * DC + chb);
            #pragma unroll
            for (int i = 0; i < 4; i++) cp16(dst + i * 16, src + i * 16);
            if (t < 32) cp16(sptr(&ksqr[nb * 128 + t * 4]),
                             g_ksq + b * LK + kbase + (kb + 1) * 128 + t * 4);
            cp_commit();
        }

        const uint8_t* kbuf = kcs + (kb & 1) * QT8_BYTES;
        const float*   kraw = ksqr + (kb & 1) * 128;
        const int k0t = kbase + kb * 128;

        float acc[4][4][4];
        #pragma unroll
        for (int i = 0; i < 4; i++)
            #pragma unroll
            for (int j = 0; j < 4; j++)
                #pragma unroll
                for (int c = 0; c < 4; c++) acc[i][j][c] = 0.f;

        #pragma unroll
        for (int ks = 0; ks < 4; ks++) {
            const int k0b = ks * 32;                 // 32 bytes = 32 fp8 k-values
            uint32_t A[4][4], Bf[2][4];
            #pragma unroll
            for (int ms = 0; ms < 4; ms++)
                ldsm4(A[ms][0], A[ms][1], A[ms][2], A[ms][3],
                      sptr(qts + (m0 + ms * 16 + arow) * PS8 + k0b + acolb));
            #pragma unroll
            for (int P = 0; P < 2; P++)
                ldsm4(Bf[P][0], Bf[P][1], Bf[P][2], Bf[P][3],
                      sptr(kbuf + (n0 + P * 16 + brow16) * PS8 + k0b + bcolb));
            #pragma unroll
            for (int ms = 0; ms < 4; ms++)
                #pragma unroll
                for (int P = 0; P < 2; P++) {
                    mma16832fp8(acc[ms][2*P][0], acc[ms][2*P][1], acc[ms][2*P][2], acc[ms][2*P][3],
                                A[ms][0], A[ms][1], A[ms][2], A[ms][3], Bf[P][0], Bf[P][1]);
                    mma16832fp8(acc[ms][2*P+1][0], acc[ms][2*P+1][1], acc[ms][2*P+1][2], acc[ms][2*P+1][3],
                                A[ms][0], A[ms][1], A[ms][2], A[ms][3], Bf[P][2], Bf[P][3]);
                }
        }

        // epilogue: thread owns 4 consecutive logical cols per tile-pair
        #pragma unroll
        for (int ms = 0; ms < 4; ms++) {
            const int rA = m0 + ms * 16 + gid, rB = rA + 8;
            const float qsA = qsqs[rA], qsB = qsqs[rB];
            const float rqA = rqs[rA],  rqB = rqs[rB];
            const size_t baseA = ((size_t)(b * LQ + q0 + rA)) * LK + k0t;
            const size_t baseB = baseA + (size_t)8 * LK;
            #pragma unroll
            for (int P = 0; P < 2; P++) {
                const int c0 = n0 + P * 16 + 4 * tid2;
                const float4 ks4 = *(const float4*)&kraw[c0];
                float vA[4] = { acc[ms][2*P][0], acc[ms][2*P][1], acc[ms][2*P+1][0], acc[ms][2*P+1][1] };
                float vB[4] = { acc[ms][2*P][2], acc[ms][2*P][3], acc[ms][2*P+1][2], acc[ms][2*P+1][3] };
                const float ksv[4] = { ks4.x, ks4.y, ks4.z, ks4.w };

                float dA[4], dB[4];
                bool bad = false;
                #pragma unroll
                for (int j = 0; j < 4; j++) {
                    const float rkj = 1.f - fminf(ksv[j], 1.f - EPSF);
                    float uA = 2.f * fmaxf(fmaf(-2.f, vA[j], qsA + ksv[j]), 0.f);
                    float nA = fmaf(rqA, rkj, EPSF);
                    float uB = 2.f * fmaxf(fmaf(-2.f, vB[j], qsB + ksv[j]), 0.f);
                    float nB = fmaf(rqB, rkj, EPSF);
                    dA[j] = LN2F * (1.f + fast_lg2(uA + nA) - fast_lg2(nA));
                    dB[j] = LN2F * (1.f + fast_lg2(uB + nB) - fast_lg2(nB));
                    bad |= (uA < 100.f * nA) | (uB < 100.f * nB);
                }
                if (bad) {   // exact path (cold)
                    #pragma unroll
                    for (int j = 0; j < 4; j++) {
                        const float rkj = 1.f - fminf(ksv[j], 1.f - EPSF);
                        float uA = 2.f * fmaxf(fmaf(-2.f, vA[j], qsA + ksv[j]), 0.f);
                        float nA = fmaf(rqA, rkj, EPSF);
                        float tA = uA * fast_rcp(nA);
                        float sA = fast_sqrt(fmaf(tA, tA, 2.f * tA));
                        dA[j] = LN2F * fast_lg2(1.f + tA + sA);
                        float uB = 2.f * fmaxf(fmaf(-2.f, vB[j], qsB + ksv[j]), 0.f);
                        float nB = fmaf(rqB, rkj, EPSF);
                        float tB = uB * fast_rcp(nB);
                        float sB = fast_sqrt(fmaf(tB, tB, 2.f * tB));
                        dB[j] = LN2F * fast_lg2(1.f + tB + sB);
                    }
                }
                __stcs((float4*)(out + baseA + c0), make_float4(dA[0], dA[1], dA[2], dA[3]));
                __stcs((float4*)(out + baseB + c0), make_float4(dB[0], dB[1], dB[2], dB[3]));
            }
        }
        __syncthreads();
    }
}

// ---------------- launch ----------------
extern "C" void kernel_launch(void* const* d_in, const int* in_sizes, int n_in,
                              void* d_out, int out_size) {
    const float* q   = (const float*)d_in[0];
    const int*   kq  = (const int*)d_in[1];
    const float* ksc = (const float*)d_in[2];
    const float* kz  = (const float*)d_in[3];
    const float* W   = (const float*)d_in[4];
    float* out = (float*)d_out;
    (void)in_sizes; (void)n_in; (void)out_size;

    cudaFuncSetAttribute(k_prepq, cudaFuncAttributeMaxDynamicSharedMemorySize, SMEM_PREPQ);
    cudaFuncSetAttribute(k_prepk, cudaFuncAttributeMaxDynamicSharedMemorySize, SMEM_PREPK);
    cudaFuncSetAttribute(k_main,  cudaFuncAttributeMaxDynamicSharedMemorySize, SMEM_MAIN);

    k_G<<<DC, 256>>>(W);
    k_prepq<<<(B_ * LQ) / 128, 256, SMEM_PREPQ>>>(q);
    k_prepk<<<(B_ * LK) / 128, 256, SMEM_PREPK>>>(kq, ksc, kz);
    k_main<<<dim3(LK / (128 * KB), LQ / 128, B_), 256, SMEM_MAIN>>>(out);
}

// round 9
// speedup vs baseline: 1.6066x; 1.1760x over previous
#include <cuda_runtime.h>
#include <cuda_bf16.h>
#include <cstdint>
#include <cmath>

#define B_   8
#define LQ   1024
#define LK   8192
#define D_   256
#define DC   128
#define EPSF 1e-6f
#define LN2F 0.69314718055994531f

// ---------------- scratch (no allocations allowed) ----------------
__device__ uint8_t        g_qt8[B_ * LQ * DC];    // q~ = q @ W_up, e4m3 (1 MB)
__device__ float          g_qsq[B_ * LQ];
__device__ uint8_t        g_kc8[B_ * LK * DC];    // dequantized codes, e4m3 (8 MB)
__device__ float          g_ksq[B_ * LK];
__device__ __nv_bfloat16  g_G[DC * DC];           // G = W^T W (bf16)
__device__ __nv_bfloat16  g_Wt[DC * D_];          // W^T (c-major)

// ---------------- fast math ----------------
__device__ __forceinline__ float fast_rcp(float x)  { float r; asm("rcp.approx.f32 %0, %1;"  : "=f"(r) : "f"(x)); return r; }
__device__ __forceinline__ float fast_sqrt(float x) { float r; asm("sqrt.approx.f32 %0, %1;" : "=f"(r) : "f"(x)); return r; }
__device__ __forceinline__ float fast_lg2(float x)  { float r; asm("lg2.approx.f32 %0, %1;"  : "=f"(r) : "f"(x)); return r; }
__device__ __forceinline__ uint16_t pack_e4m3x2(float lo, float hi) {
    uint16_t u;
    asm("cvt.rn.satfinite.e4m3x2.f32 %0, %1, %2;" : "=h"(u) : "f"(hi), "f"(lo));
    return u;
}

// ---------------- mma helpers ----------------
__device__ __forceinline__ uint32_t sptr(const void* p) {
    return (uint32_t)__cvta_generic_to_shared(p);
}
__device__ __forceinline__ void ldsm4(uint32_t& a0, uint32_t& a1, uint32_t& a2, uint32_t& a3, uint32_t addr) {
    asm volatile("ldmatrix.sync.aligned.m8n8.x4.shared.b16 {%0,%1,%2,%3}, [%4];"
                 : "=r"(a0), "=r"(a1), "=r"(a2), "=r"(a3) : "r"(addr));
}
__device__ __forceinline__ void ldsm2(uint32_t& b0, uint32_t& b1, uint32_t addr) {
    asm volatile("ldmatrix.sync.aligned.m8n8.x2.shared.b16 {%0,%1}, [%2];"
                 : "=r"(b0), "=r"(b1) : "r"(addr));
}
__device__ __forceinline__ void mma16816(float& c0, float& c1, float& c2, float& c3,
                                         uint32_t a0, uint32_t a1, uint32_t a2, uint32_t a3,
                                         uint32_t b0, uint32_t b1) {
    asm volatile("mma.sync.aligned.m16n8k16.row.col.f32.bf16.bf16.f32 "
                 "{%0,%1,%2,%3}, {%4,%5,%6,%7}, {%8,%9}, {%0,%1,%2,%3};"
                 : "+f"(c0), "+f"(c1), "+f"(c2), "+f"(c3)
                 : "r"(a0), "r"(a1), "r"(a2), "r"(a3), "r"(b0), "r"(b1));
}
__device__ __forceinline__ void mma16832fp8(float& c0, float& c1, float& c2, float& c3,
                                            uint32_t a0, uint32_t a1, uint32_t a2, uint32_t a3,
                                            uint32_t b0, uint32_t b1) {
    asm volatile("mma.sync.aligned.m16n8k32.row.col.f32.e4m3.e4m3.f32 "
                 "{%0,%1,%2,%3}, {%4,%5,%6,%7}, {%8,%9}, {%0,%1,%2,%3};"
                 : "+f"(c0), "+f"(c1), "+f"(c2), "+f"(c3)
                 : "r"(a0), "r"(a1), "r"(a2), "r"(a3), "r"(b0), "r"(b1));
}
__device__ __forceinline__ void cp16(uint32_t dst, const void* src) {
    asm volatile("cp.async.cg.shared.global [%0], [%1], 16;" :: "r"(dst), "l"(src));
}
__device__ __forceinline__ void cp_commit() { asm volatile("cp.async.commit_group;" ::: "memory"); }
__device__ __forceinline__ void cp_wait0()  { asm volatile("cp.async.wait_group 0;" ::: "memory"); }

// ---------------- kernel 1: G = W^T W (bf16) + Wt bf16 ----------------
__global__ void k_G(const float* __restrict__ W) {
    __shared__ float col[D_];
    __shared__ float red[256];
    const int c1 = blockIdx.x;
    const int t  = threadIdx.x;
    const int c2 = t & 127, h = t >> 7;

    float wv = W[t * DC + c1];
    col[t] = wv;
    g_Wt[c1 * D_ + t] = __float2bfloat16(wv);
    __syncthreads();

    float acc = 0.f;
    const int d0 = h * 128;
    #pragma unroll 8
    for (int d = 0; d < 128; d++) acc += col[d0 + d] * W[(d0 + d) * DC + c2];
    red[t] = acc;
    __syncthreads();
    if (h == 0) g_G[c1 * DC + c2] = __float2bfloat16(red[c2] + red[c2 + 128]);
}

// ---------------- kernel 2: q~ = q @ W via MMA + q_sq (outputs e4m3) ----------------
#define QSTRIDE 264
#define SMEM_PREPQ (128 * QSTRIDE * 2 * 2 + 256 * 4 + 128 * 4 + 256)

__global__ void k_prepq(const float* __restrict__ q) {
    extern __shared__ char sm[];
    __nv_bfloat16* qs  = (__nv_bfloat16*)sm;
    __nv_bfloat16* Wts = qs + 128 * QSTRIDE;
    float*         par = (float*)(Wts + 128 * QSTRIDE);
    float*         qsq = par + 256;

    const int t  = threadIdx.x;
    const int r0 = blockIdx.x * 128;

    {
        const float4* src = (const float4*)(q + (size_t)r0 * D_);
        #pragma unroll
        for (int i = 0; i < 32; i++) {
            int idx = t + i * 256;
            int row = idx >> 6, c4 = (idx & 63) * 4;
            float4 v = src[idx];
            *(__nv_bfloat162*)&qs[row * QSTRIDE + c4]     = __floats2bfloat162_rn(v.x, v.y);
            *(__nv_bfloat162*)&qs[row * QSTRIDE + c4 + 2] = __floats2bfloat162_rn(v.z, v.w);
        }
    }
    {
        const float4* rowp = (const float4*)(q + (size_t)(r0 + (t >> 1)) * D_) + (t & 1) * 32;
        float ss = 0.f;
        #pragma unroll 8
        for (int i = 0; i < 32; i++) {
            float4 v = rowp[i];
            ss += v.x * v.x + v.y * v.y + v.z * v.z + v.w * v.w;
        }
        par[t] = ss;
    }
    {
        #pragma unroll
        for (int i = 0; i < 16; i++) {
            int idx = t + i * 256;
            int r = idx >> 5, c8 = (idx & 31) * 8;
            *(uint4*)&Wts[r * QSTRIDE + c8] = ((const uint4*)g_Wt)[idx];
        }
    }
    __syncthreads();
    if (t < 128) qsq[t] = par[2 * t] + par[2 * t + 1];

    const int w = t >> 5, lane = t & 31;
    const int m0 = (w >> 2) * 64, n0 = (w & 3) * 32;
    const int gid = lane >> 2, tid2 = lane & 3;
    const int arow = lane & 15, acol = ((lane >> 4) << 3);
    const int brow = lane & 7,  bcol = (((lane >> 3) & 1) << 3);

    float acc[4][4][4];
    #pragma unroll
    for (int i = 0; i < 4; i++)
        #pragma unroll
        for (int j = 0; j < 4; j++)
            #pragma unroll
            for (int c = 0; c < 4; c++) acc[i][j][c] = 0.f;

    #pragma unroll
    for (int ks = 0; ks < 16; ks++) {
        const int k0 = ks * 16;
        uint32_t A[4][4], Bf[4][2];
        #pragma unroll
        for (int ms = 0; ms < 4; ms++)
            ldsm4(A[ms][0], A[ms][1], A[ms][2], A[ms][3],
                  sptr(&qs[(m0 + ms * 16 + arow) * QSTRIDE + k0 + acol]));
        #pragma unroll
        for (int ns = 0; ns < 4; ns++)
            ldsm2(Bf[ns][0], Bf[ns][1],
                  sptr(&Wts[(n0 + ns * 8 + brow) * QSTRIDE + k0 + bcol]));
        #pragma unroll
        for (int ms = 0; ms < 4; ms++)
            #pragma unroll
            for (int ns = 0; ns < 4; ns++)
                mma16816(acc[ms][ns][0], acc[ms][ns][1], acc[ms][ns][2], acc[ms][ns][3],
                         A[ms][0], A[ms][1], A[ms][2], A[ms][3], Bf[ns][0], Bf[ns][1]);
    }

    #pragma unroll
    for (int ms = 0; ms < 4; ms++) {
        const int rA = m0 + ms * 16 + gid, rB = rA + 8;
        #pragma unroll
        for (int ns = 0; ns < 4; ns++) {
            const int c0 = n0 + ns * 8 + tid2 * 2;
            *(uint16_t*)&g_qt8[(size_t)(r0 + rA) * DC + c0] = pack_e4m3x2(acc[ms][ns][0], acc[ms][ns][1]);
            *(uint16_t*)&g_qt8[(size_t)(r0 + rB) * DC + c0] = pack_e4m3x2(acc[ms][ns][2], acc[ms][ns][3]);
        }
    }
    __syncthreads();
    if (t < 128) g_qsq[r0 + t] = qsq[t];
}

// ---------------- kernel 3: dequant codes + k_sq = kc^T G kc (outputs e4m3) ----------------
#define PSTRIDE 136
#define SMEM_PREPK (2 * 128 * PSTRIDE * 2 + 512)

__global__ void k_prepk(const int* __restrict__ kq,
                        const float* __restrict__ kscale,
                        const float* __restrict__ kzero) {
    extern __shared__ char sm[];
    __nv_bfloat16* kcs  = (__nv_bfloat16*)sm;
    __nv_bfloat16* Gs   = kcs + 128 * PSTRIDE;
    float*         ksqs = (float*)(Gs + 128 * PSTRIDE);

    const int t    = threadIdx.x;
    const int row0 = blockIdx.x * 128;
    const int b    = row0 / LK;

    {
        const int c4 = (t & 31) * 4;
        const float4 sc = *(const float4*)(kscale + b * DC + c4);
        const float4 zr = *(const float4*)(kzero + b * DC + c4);
        const int rb = t >> 5;
        #pragma unroll
        for (int i = 0; i < 16; i++) {
            const int r = rb + i * 8;
            const int4 code = *(const int4*)(kq + (size_t)(row0 + r) * DC + c4);
            float v0 = sc.x * ((float)code.x - zr.x);
            float v1 = sc.y * ((float)code.y - zr.y);
            float v2 = sc.z * ((float)code.z - zr.z);
            float v3 = sc.w * ((float)code.w - zr.w);
            __nv_bfloat162 p0, p1;
            p0.x = __float2bfloat16(v0); p0.y = __float2bfloat16(v1);
            p1.x = __float2bfloat16(v2); p1.y = __float2bfloat16(v3);
            *(__nv_bfloat162*)&kcs[r * PSTRIDE + c4]     = p0;
            *(__nv_bfloat162*)&kcs[r * PSTRIDE + c4 + 2] = p1;
            uint32_t pk = (uint32_t)pack_e4m3x2(v0, v1) | ((uint32_t)pack_e4m3x2(v2, v3) << 16);
            *(uint32_t*)&g_kc8[(size_t)(row0 + r) * DC + c4] = pk;
        }
    }
    {
        const int r = t >> 1, ch = (t & 1) * 64;
        const uint4* src = (const uint4*)(g_G + r * DC + ch);
        #pragma unroll
        for (int i = 0; i < 8; i++) *(uint4*)&Gs[r * PSTRIDE + ch + i * 8] = src[i];
    }
    if (t < 128) ksqs[t] = 0.f;
    __syncthreads();

    const int w = t >> 5, lane = t & 31;
    const int m0 = (w >> 2) * 64, n0 = (w & 3) * 32;
    const int gid = lane >> 2, tid2 = lane & 3;
    const int arow = lane & 15, acol = ((lane >> 4) << 3);
    const int brow = lane & 7,  bcol = (((lane >> 3) & 1) << 3);

    float acc[4][4][4];
    #pragma unroll
    for (int i = 0; i < 4; i++)
        #pragma unroll
        for (int j = 0; j < 4; j++)
            #pragma unroll
            for (int c = 0; c < 4; c++) acc[i][j][c] = 0.f;

    #pragma unroll
    for (int ks = 0; ks < 8; ks++) {
        const int k0 = ks * 16;
        uint32_t A[4][4], Bf[4][2];
        #pragma unroll
        for (int ms = 0; ms < 4; ms++)
            ldsm4(A[ms][0], A[ms][1], A[ms][2], A[ms][3],
                  sptr(&kcs[(m0 + ms * 16 + arow) * PSTRIDE + k0 + acol]));
        #pragma unroll
        for (int ns = 0; ns < 4; ns++)
            ldsm2(Bf[ns][0], Bf[ns][1],
                  sptr(&Gs[(n0 + ns * 8 + brow) * PSTRIDE + k0 + bcol]));
        #pragma unroll
        for (int ms = 0; ms < 4; ms++)
            #pragma unroll
            for (int ns = 0; ns < 4; ns++)
                mma16816(acc[ms][ns][0], acc[ms][ns][1], acc[ms][ns][2], acc[ms][ns][3],
                         A[ms][0], A[ms][1], A[ms][2], A[ms][3], Bf[ns][0], Bf[ns][1]);
    }

    #pragma unroll
    for (int ms = 0; ms < 4; ms++) {
        const int rA = m0 + ms * 16 + gid, rB = rA + 8;
        float sA = 0.f, sB = 0.f;
        #pragma unroll
        for (int ns = 0; ns < 4; ns++) {
            const int c0 = n0 + ns * 8 + tid2 * 2;
            sA += acc[ms][ns][0] * __bfloat162float(kcs[rA * PSTRIDE + c0]);
            sA += acc[ms][ns][1] * __bfloat162float(kcs[rA * PSTRIDE + c0 + 1]);
            sB += acc[ms][ns][2] * __bfloat162float(kcs[rB * PSTRIDE + c0]);
            sB += acc[ms][ns][3] * __bfloat162float(kcs[rB * PSTRIDE + c0 + 1]);
        }
        atomicAdd(&ksqs[rA], sA);
        atomicAdd(&ksqs[rB], sB);
    }
    __syncthreads();
    if (t < 128) g_ksq[row0 + t] = ksqs[t];
}

// ---------------- kernel 4: main — FP8 MMA + uniform-denominator fast epilogue ----------------
#define KB 2
#define PS8 144
#define QT8_BYTES (128 * PS8)
#define SM_KT8    QT8_BYTES
#define SM_NRM    (QT8_BYTES * 3)
#define SMEM_MAIN (QT8_BYTES * 3 + 4 * 128 * 4 + 256)

__global__ void __launch_bounds__(256, 2) k_main(float* __restrict__ out) {
    extern __shared__ char sm[];
    uint8_t* qts  = (uint8_t*)sm;                      // [128][144] e4m3
    uint8_t* kcs  = (uint8_t*)sm + SM_KT8;             // [2][128][144] e4m3, rows permuted
    float*   qsqs = (float*)(sm + SM_NRM);             // [128]
    float*   rqs  = qsqs + 128;                        // [128]
    float*   ksqr = rqs + 128;                         // [2][128]

    const int t = threadIdx.x;                         // 256
    const int kbb = blockIdx.x, qb = blockIdx.y, b = blockIdx.z;
    const int q0 = qb * 128, kbase = kbb * (128 * KB);

    const int r  = t >> 1, chb = (t & 1) * 64;
    const int l  = r & 15;
    const int pr = (r & ~15) | (((l >> 1) & 1) * 8 + ((l >> 2) << 1) + (l & 1));

    // q tile (once)
    {
        const uint4* s1 = (const uint4*)(g_qt8 + ((size_t)(b * LQ + q0 + r)) * DC + chb);
        #pragma unroll
        for (int i = 0; i < 4; i++) *(uint4*)(qts + r * PS8 + chb + i * 16) = s1[i];
    }
    if (t < 128) {
        float qs = g_qsq[b * LQ + q0 + t];
        qsqs[t] = qs;
        rqs[t] = 1.f - fminf(qs, 1.f - EPSF);
    }

    // prefetch k buffer 0
    {
        const uint32_t dst = sptr(kcs + pr * PS8 + chb);
        const char* src = (const char*)(g_kc8 + ((size_t)(b * LK + kbase + r)) * DC + chb);
        #pragma unroll
        for (int i = 0; i < 4; i++) cp16(dst + i * 16, src + i * 16);
        if (t < 32) cp16(sptr(&ksqr[t * 4]), g_ksq + b * LK + kbase + t * 4);
    }
    cp_commit();

    const int w = t >> 5, lane = t & 31;
    const int m0 = (w >> 2) * 64, nw0 = (w & 3) * 32;
    const int gid = lane >> 2, tid2 = lane & 3;
    const int arow = lane & 15, acolb = ((lane >> 4) << 4);
    const int brow16 = (lane & 7) + ((lane >> 4) << 3);
    const int bcolb = (((lane >> 3) & 1) << 4);

    // uniform-denominator constants (n = EPS^2 + EPS when all norms >= 1-EPS)
    const float N0C = EPSF + EPSF * EPSF;
    const float H0  = 0.5f * N0C;
    const float C0  = LN2F * (2.f - fast_lg2(N0C));
    const float TH  = 50.5f * N0C;
    const float I2N = 2.f * fast_rcp(N0C);

    for (int kb = 0; kb < KB; kb++) {
        cp_wait0();
        __syncthreads();

        if (kb + 1 < KB) {
            const int nb = (kb + 1) & 1;
            const uint32_t dst = sptr(kcs + nb * QT8_BYTES + pr * PS8 + chb);
            const char* src = (const char*)(g_kc8 + ((size_t)(b * LK + kbase + (kb + 1) * 128 + r)) * DC + chb);
            #pragma unroll
            for (int i = 0; i < 4; i++) cp16(dst + i * 16, src + i * 16);
            if (t < 32) cp16(sptr(&ksqr[nb * 128 + t * 4]),
                             g_ksq + b * LK + kbase + (kb + 1) * 128 + t * 4);
            cp_commit();
        }

        const uint8_t* kbuf = kcs + (kb & 1) * QT8_BYTES;
        const float*   kraw = ksqr + (kb & 1) * 128;
        const int k0t = kbase + kb * 128;

        float acc[4][4][4];
        #pragma unroll
        for (int i = 0; i < 4; i++)
            #pragma unroll
            for (int j = 0; j < 4; j++)
                #pragma unroll
                for (int c = 0; c < 4; c++) acc[i][j][c] = 0.f;

        #pragma unroll
        for (int ks = 0; ks < 4; ks++) {
            const int k0b = ks * 32;
            uint32_t A[4][4], Bf[2][4];
            #pragma unroll
            for (int ms = 0; ms < 4; ms++)
                ldsm4(A[ms][0], A[ms][1], A[ms][2], A[ms][3],
                      sptr(qts + (m0 + ms * 16 + arow) * PS8 + k0b + acolb));
            #pragma unroll
            for (int P = 0; P < 2; P++)
                ldsm4(Bf[P][0], Bf[P][1], Bf[P][2], Bf[P][3],
                      sptr(kbuf + (nw0 + P * 16 + brow16) * PS8 + k0b + bcolb));
            #pragma unroll
            for (int ms = 0; ms < 4; ms++)
                #pragma unroll
                for (int P = 0; P < 2; P++) {
                    mma16832fp8(acc[ms][2*P][0], acc[ms][2*P][1], acc[ms][2*P][2], acc[ms][2*P][3],
                                A[ms][0], A[ms][1], A[ms][2], A[ms][3], Bf[P][0], Bf[P][1]);
                    mma16832fp8(acc[ms][2*P+1][0], acc[ms][2*P+1][1], acc[ms][2*P+1][2], acc[ms][2*P+1][3],
                                A[ms][0], A[ms][1], A[ms][2], A[ms][3], Bf[P][2], Bf[P][3]);
                }
        }

        // ---- epilogue ----
        float4 ks4[2];
        ks4[0] = *(const float4*)&kraw[nw0 + 4 * tid2];
        ks4[1] = *(const float4*)&kraw[nw0 + 16 + 4 * tid2];

        // uniformity check: all 8 rows + 8 cols of this thread have norm >= 1-EPS
        bool uni = ks4[0].x >= 1.f - EPSF && ks4[0].y >= 1.f - EPSF &&
                   ks4[0].z >= 1.f - EPSF && ks4[0].w >= 1.f - EPSF &&
                   ks4[1].x >= 1.f - EPSF && ks4[1].y >= 1.f - EPSF &&
                   ks4[1].z >= 1.f - EPSF && ks4[1].w >= 1.f - EPSF;
        #pragma unroll
        for (int ms = 0; ms < 4; ms++) {
            const int rA = m0 + ms * 16 + gid;
            uni = uni && (qsqs[rA] >= 1.f - EPSF) && (qsqs[rA + 8] >= 1.f - EPSF);
        }

        if (uni) {
            // fast path: denominator is the constant N0C for every element
            #pragma unroll
            for (int ms = 0; ms < 4; ms++) {
                const int rA = m0 + ms * 16 + gid, rB = rA + 8;
                const float aA = qsqs[rA] + H0, aB = qsqs[rB] + H0;
                const size_t baseA = ((size_t)(b * LQ + q0 + rA)) * LK + k0t;
                const size_t baseB = baseA + (size_t)8 * LK;
                #pragma unroll
                for (int P = 0; P < 2; P++) {
                    const int c0 = nw0 + P * 16 + 4 * tid2;
                    const float4 kk = ks4[P];
                    const float ksv[4] = { kk.x, kk.y, kk.z, kk.w };
                    float vA[4] = { acc[ms][2*P][0], acc[ms][2*P][1], acc[ms][2*P+1][0], acc[ms][2*P+1][1] };
                    float vB[4] = { acc[ms][2*P][2], acc[ms][2*P][3], acc[ms][2*P+1][2], acc[ms][2*P+1][3] };

                    float xA[4], xB[4], dA[4], dB[4];
                    bool bad = false;
                    #pragma unroll
                    for (int j = 0; j < 4; j++) {
                        xA[j] = fmaxf(fmaf(-2.f, vA[j], aA + ksv[j]), H0);
                        xB[j] = fmaxf(fmaf(-2.f, vB[j], aB + ksv[j]), H0);
                        bad |= (xA[j] < TH) | (xB[j] < TH);
                        dA[j] = fmaf(fast_lg2(xA[j]), LN2F, C0);
                        dB[j] = fmaf(fast_lg2(xB[j]), LN2F, C0);
                    }
                    if (bad) {   // exact acosh for small-t elements (cold)
                        #pragma unroll
                        for (int j = 0; j < 4; j++) {
                            float tA = (xA[j] - H0) * I2N;
                            float sA = fast_sqrt(fmaf(tA, tA, 2.f * tA));
                            dA[j] = LN2F * fast_lg2(1.f + tA + sA);
                            float tB = (xB[j] - H0) * I2N;
                            float sB = fast_sqrt(fmaf(tB, tB, 2.f * tB));
                            dB[j] = LN2F * fast_lg2(1.f + tB + sB);
                        }
                    }
                    __stcs((float4*)(out + baseA + c0), make_float4(dA[0], dA[1], dA[2], dA[3]));
                    __stcs((float4*)(out + baseB + c0), make_float4(dB[0], dB[1], dB[2], dB[3]));
                }
            }
        } else {
            // general path (cold for this data distribution)
            #pragma unroll
            for (int ms = 0; ms < 4; ms++) {
                const int rA = m0 + ms * 16 + gid, rB = rA + 8;
                const float qsA = qsqs[rA], qsB = qsqs[rB];
                const float rqA = rqs[rA],  rqB = rqs[rB];
                const size_t baseA = ((size_t)(b * LQ + q0 + rA)) * LK + k0t;
                const size_t baseB = baseA + (size_t)8 * LK;
                #pragma unroll
                for (int P = 0; P < 2; P++) {
                    const int c0 = nw0 + P * 16 + 4 * tid2;
                    const float4 kk = ks4[P];
                    const float ksv[4] = { kk.x, kk.y, kk.z, kk.w };
                    float vA[4] = { acc[ms][2*P][0], acc[ms][2*P][1], acc[ms][2*P+1][0], acc[ms][2*P+1][1] };
                    float vB[4] = { acc[ms][2*P][2], acc[ms][2*P][3], acc[ms][2*P+1][2], acc[ms][2*P+1][3] };

                    float dA[4], dB[4];
                    #pragma unroll
                    for (int j = 0; j < 4; j++) {
                        const float rkj = 1.f - fminf(ksv[j], 1.f - EPSF);
                        float uA = 2.f * fmaxf(fmaf(-2.f, vA[j], qsA + ksv[j]), 0.f);
                        float nA = fmaf(rqA, rkj, EPSF);
                        float uB = 2.f * fmaxf(fmaf(-2.f, vB[j], qsB + ksv[j]), 0.f);
                        float nB = fmaf(rqB, rkj, EPSF);
                        if (uA >= 100.f * nA) {
                            dA[j] = LN2F * (1.f + fast_lg2(uA + nA) - fast_lg2(nA));
                        } else {
                            float tA = uA * fast_rcp(nA);
                            float sA = fast_sqrt(fmaf(tA, tA, 2.f * tA));
                            dA[j] = LN2F * fast_lg2(1.f + tA + sA);
                        }
                        if (uB >= 100.f * nB) {
                            dB[j] = LN2F * (1.f + fast_lg2(uB + nB) - fast_lg2(nB));
                        } else {
                            float tB = uB * fast_rcp(nB);
                            float sB = fast_sqrt(fmaf(tB, tB, 2.f * tB));
                            dB[j] = LN2F * fast_lg2(1.f + tB + sB);
                        }
                    }
                    __stcs((float4*)(out + baseA + c0), make_float4(dA[0], dA[1], dA[2], dA[3]));
                    __stcs((float4*)(out + baseB + c0), make_float4(dB[0], dB[1], dB[2], dB[3]));
                }
            }
        }
        __syncthreads();
    }
}

// ---------------- launch ----------------
extern "C" void kernel_launch(void* const* d_in, const int* in_sizes, int n_in,
                              void* d_out, int out_size) {
    const float* q   = (const float*)d_in[0];
    const int*   kq  = (const int*)d_in[1];
    const float* ksc = (const float*)d_in[2];
    const float* kz  = (const float*)d_in[3];
    const float* W   = (const float*)d_in[4];
    float* out = (float*)d_out;
    (void)in_sizes; (void)n_in; (void)out_size;

    cudaFuncSetAttribute(k_prepq, cudaFuncAttributeMaxDynamicSharedMemorySize, SMEM_PREPQ);
    cudaFuncSetAttribute(k_prepk, cudaFuncAttributeMaxDynamicSharedMemorySize, SMEM_PREPK);
    cudaFuncSetAttribute(k_main,  cudaFuncAttributeMaxDynamicSharedMemorySize, SMEM_MAIN);

    k_G<<<DC, 256>>>(W);
    k_prepq<<<(B_ * LQ) / 128, 256, SMEM_PREPQ>>>(q);
    k_prepk<<<(B_ * LK) / 128, 256, SMEM_PREPK>>>(kq, ksc, kz);
    k_main<<<dim3(LK / (128 * KB), LQ / 128, B_), 256, SMEM_MAIN>>>(out);
}

// round 10
// speedup vs baseline: 1.7249x; 1.0737x over previous
#include <cuda_runtime.h>
#include <cuda_bf16.h>
#include <cstdint>
#include <cmath>

#define B_   8
#define LQ   1024
#define LK   8192
#define D_   256
#define DC   128
#define EPSF 1e-6f
#define LN2F 0.69314718055994531f

// ---------------- scratch (no allocations allowed) ----------------
__device__ uint8_t        g_qt8[B_ * LQ * DC];    // q~ = q @ W_up, e4m3 (1 MB)
__device__ float          g_qsq[B_ * LQ];
__device__ uint8_t        g_kc8[B_ * LK * DC];    // dequantized codes, e4m3 (8 MB)
__device__ float          g_ksq[B_ * LK];
__device__ __nv_bfloat16  g_G[DC * DC];           // G = W^T W (bf16)
__device__ __nv_bfloat16  g_Wt[DC * D_];          // W^T (c-major)

// ---------------- fast math ----------------
__device__ __forceinline__ float fast_rcp(float x)  { float r; asm("rcp.approx.f32 %0, %1;"  : "=f"(r) : "f"(x)); return r; }
__device__ __forceinline__ float fast_sqrt(float x) { float r; asm("sqrt.approx.f32 %0, %1;" : "=f"(r) : "f"(x)); return r; }
__device__ __forceinline__ float fast_lg2(float x)  { float r; asm("lg2.approx.f32 %0, %1;"  : "=f"(r) : "f"(x)); return r; }
__device__ __forceinline__ uint16_t pack_e4m3x2(float lo, float hi) {
    uint16_t u;
    asm("cvt.rn.satfinite.e4m3x2.f32 %0, %1, %2;" : "=h"(u) : "f"(hi), "f"(lo));
    return u;
}

// ---------------- mma helpers ----------------
__device__ __forceinline__ uint32_t sptr(const void* p) {
    return (uint32_t)__cvta_generic_to_shared(p);
}
__device__ __forceinline__ void ldsm4(uint32_t& a0, uint32_t& a1, uint32_t& a2, uint32_t& a3, uint32_t addr) {
    asm volatile("ldmatrix.sync.aligned.m8n8.x4.shared.b16 {%0,%1,%2,%3}, [%4];"
                 : "=r"(a0), "=r"(a1), "=r"(a2), "=r"(a3) : "r"(addr));
}
__device__ __forceinline__ void ldsm2(uint32_t& b0, uint32_t& b1, uint32_t addr) {
    asm volatile("ldmatrix.sync.aligned.m8n8.x2.shared.b16 {%0,%1}, [%2];"
                 : "=r"(b0), "=r"(b1) : "r"(addr));
}
__device__ __forceinline__ void mma16816(float& c0, float& c1, float& c2, float& c3,
                                         uint32_t a0, uint32_t a1, uint32_t a2, uint32_t a3,
                                         uint32_t b0, uint32_t b1) {
    asm volatile("mma.sync.aligned.m16n8k16.row.col.f32.bf16.bf16.f32 "
                 "{%0,%1,%2,%3}, {%4,%5,%6,%7}, {%8,%9}, {%0,%1,%2,%3};"
                 : "+f"(c0), "+f"(c1), "+f"(c2), "+f"(c3)
                 : "r"(a0), "r"(a1), "r"(a2), "r"(a3), "r"(b0), "r"(b1));
}
__device__ __forceinline__ void mma16832fp8(float& c0, float& c1, float& c2, float& c3,
                                            uint32_t a0, uint32_t a1, uint32_t a2, uint32_t a3,
                                            uint32_t b0, uint32_t b1) {
    asm volatile("mma.sync.aligned.m16n8k32.row.col.f32.e4m3.e4m3.f32 "
                 "{%0,%1,%2,%3}, {%4,%5,%6,%7}, {%8,%9}, {%0,%1,%2,%3};"
                 : "+f"(c0), "+f"(c1), "+f"(c2), "+f"(c3)
                 : "r"(a0), "r"(a1), "r"(a2), "r"(a3), "r"(b0), "r"(b1));
}
__device__ __forceinline__ void cp16(uint32_t dst, const void* src) {
    asm volatile("cp.async.cg.shared.global [%0], [%1], 16;" :: "r"(dst), "l"(src));
}
__device__ __forceinline__ void cp_commit() { asm volatile("cp.async.commit_group;" ::: "memory"); }
__device__ __forceinline__ void cp_wait0()  { asm volatile("cp.async.wait_group 0;" ::: "memory"); }

// ---------------- kernel 1: G = W^T W (bf16) + Wt bf16 ----------------
__global__ void k_G(const float* __restrict__ W) {
    __shared__ float col[D_];
    __shared__ float red[256];
    const int c1 = blockIdx.x;
    const int t  = threadIdx.x;
    const int c2 = t & 127, h = t >> 7;

    float wv = W[t * DC + c1];
    col[t] = wv;
    g_Wt[c1 * D_ + t] = __float2bfloat16(wv);
    __syncthreads();

    float acc = 0.f;
    const int d0 = h * 128;
    #pragma unroll 8
    for (int d = 0; d < 128; d++) acc += col[d0 + d] * W[(d0 + d) * DC + c2];
    red[t] = acc;
    __syncthreads();
    if (h == 0) g_G[c1 * DC + c2] = __float2bfloat16(red[c2] + red[c2 + 128]);
}

// ---------------- kernel 2: q~ = q @ W via MMA + q_sq (64 rows/block, e4m3 out) ----------------
#define QR 64
#define QSTRIDE 264
#define SMEM_PREPQ (QR * QSTRIDE * 2 + 128 * QSTRIDE * 2 + 128 * 4 + QR * 4 + 256)

__global__ void k_prepq(const float* __restrict__ q) {
    extern __shared__ char sm[];
    __nv_bfloat16* qs  = (__nv_bfloat16*)sm;                 // [64][264]
    __nv_bfloat16* Wts = qs + QR * QSTRIDE;                  // [128][264]
    float*         par = (float*)(Wts + 128 * QSTRIDE);      // [128]
    float*         qsq = par + 128;                          // [64]

    const int t  = threadIdx.x;          // 256
    const int r0 = blockIdx.x * QR;      // 128 blocks

    // load q tile (64 x 256 fp32) -> bf16 smem
    {
        const float4* src = (const float4*)(q + (size_t)r0 * D_);
        #pragma unroll
        for (int i = 0; i < 16; i++) {
            int idx = t + i * 256;                // 4096 float4
            int row = idx >> 6, c4 = (idx & 63) * 4;
            float4 v = src[idx];
            *(__nv_bfloat162*)&qs[row * QSTRIDE + c4]     = __floats2bfloat162_rn(v.x, v.y);
            *(__nv_bfloat162*)&qs[row * QSTRIDE + c4 + 2] = __floats2bfloat162_rn(v.z, v.w);
        }
    }
    // q_sq in fp32: 2 threads per row
    if (t < 128) {
        const float4* rowp = (const float4*)(q + (size_t)(r0 + (t >> 1)) * D_) + (t & 1) * 32;
        float ss = 0.f;
        #pragma unroll 8
        for (int i = 0; i < 32; i++) {
            float4 v = rowp[i];
            ss += v.x * v.x + v.y * v.y + v.z * v.z + v.w * v.w;
        }
        par[t] = ss;
    }
    // load W^T tile (64KB)
    {
        #pragma unroll
        for (int i = 0; i < 16; i++) {
            int idx = t + i * 256;                // 4096 uint4
            int r = idx >> 5, c8 = (idx & 31) * 8;
            *(uint4*)&Wts[r * QSTRIDE + c8] = ((const uint4*)g_Wt)[idx];
        }
    }
    __syncthreads();
    if (t < QR) qsq[t] = par[2 * t] + par[2 * t + 1];

    const int w = t >> 5, lane = t & 31;
    const int m0 = (w >> 2) * 32, n0 = (w & 3) * 32;
    const int gid = lane >> 2, tid2 = lane & 3;
    const int arow = lane & 15, acol = ((lane >> 4) << 3);
    const int brow = lane & 7,  bcol = (((lane >> 3) & 1) << 3);

    float acc[2][4][4];
    #pragma unroll
    for (int i = 0; i < 2; i++)
        #pragma unroll
        for (int j = 0; j < 4; j++)
            #pragma unroll
            for (int c = 0; c < 4; c++) acc[i][j][c] = 0.f;

    #pragma unroll
    for (int ks = 0; ks < 16; ks++) {
        const int k0 = ks * 16;
        uint32_t A[2][4], Bf[4][2];
        #pragma unroll
        for (int ms = 0; ms < 2; ms++)
            ldsm4(A[ms][0], A[ms][1], A[ms][2], A[ms][3],
                  sptr(&qs[(m0 + ms * 16 + arow) * QSTRIDE + k0 + acol]));
        #pragma unroll
        for (int ns = 0; ns < 4; ns++)
            ldsm2(Bf[ns][0], Bf[ns][1],
                  sptr(&Wts[(n0 + ns * 8 + brow) * QSTRIDE + k0 + bcol]));
        #pragma unroll
        for (int ms = 0; ms < 2; ms++)
            #pragma unroll
            for (int ns = 0; ns < 4; ns++)
                mma16816(acc[ms][ns][0], acc[ms][ns][1], acc[ms][ns][2], acc[ms][ns][3],
                         A[ms][0], A[ms][1], A[ms][2], A[ms][3], Bf[ns][0], Bf[ns][1]);
    }

    #pragma unroll
    for (int ms = 0; ms < 2; ms++) {
        const int rA = m0 + ms * 16 + gid, rB = rA + 8;
        #pragma unroll
        for (int ns = 0; ns < 4; ns++) {
            const int c0 = n0 + ns * 8 + tid2 * 2;
            *(uint16_t*)&g_qt8[(size_t)(r0 + rA) * DC + c0] = pack_e4m3x2(acc[ms][ns][0], acc[ms][ns][1]);
            *(uint16_t*)&g_qt8[(size_t)(r0 + rB) * DC + c0] = pack_e4m3x2(acc[ms][ns][2], acc[ms][ns][3]);
        }
    }
    __syncthreads();
    if (t < QR) g_qsq[r0 + t] = qsq[t];
}

// ---------------- kernel 3: dequant codes + k_sq = kc^T G kc (outputs e4m3) ----------------
#define PSTRIDE 136
#define SMEM_PREPK (2 * 128 * PSTRIDE * 2 + 512)

__global__ void k_prepk(const int* __restrict__ kq,
                        const float* __restrict__ kscale,
                        const float* __restrict__ kzero) {
    extern __shared__ char sm[];
    __nv_bfloat16* kcs  = (__nv_bfloat16*)sm;
    __nv_bfloat16* Gs   = kcs + 128 * PSTRIDE;
    float*         ksqs = (float*)(Gs + 128 * PSTRIDE);

    const int t    = threadIdx.x;
    const int row0 = blockIdx.x * 128;
    const int b    = row0 / LK;

    {
        const int c4 = (t & 31) * 4;
        const float4 sc = *(const float4*)(kscale + b * DC + c4);
        const float4 zr = *(const float4*)(kzero + b * DC + c4);
        const int rb = t >> 5;
        #pragma unroll
        for (int i = 0; i < 16; i++) {
            const int r = rb + i * 8;
            const int4 code = *(const int4*)(kq + (size_t)(row0 + r) * DC + c4);
            float v0 = sc.x * ((float)code.x - zr.x);
            float v1 = sc.y * ((float)code.y - zr.y);
            float v2 = sc.z * ((float)code.z - zr.z);
            float v3 = sc.w * ((float)code.w - zr.w);
            __nv_bfloat162 p0, p1;
            p0.x = __float2bfloat16(v0); p0.y = __float2bfloat16(v1);
            p1.x = __float2bfloat16(v2); p1.y = __float2bfloat16(v3);
            *(__nv_bfloat162*)&kcs[r * PSTRIDE + c4]     = p0;
            *(__nv_bfloat162*)&kcs[r * PSTRIDE + c4 + 2] = p1;
            uint32_t pk = (uint32_t)pack_e4m3x2(v0, v1) | ((uint32_t)pack_e4m3x2(v2, v3) << 16);
            *(uint32_t*)&g_kc8[(size_t)(row0 + r) * DC + c4] = pk;
        }
    }
    {
        const int r = t >> 1, ch = (t & 1) * 64;
        const uint4* src = (const uint4*)(g_G + r * DC + ch);
        #pragma unroll
        for (int i = 0; i < 8; i++) *(uint4*)&Gs[r * PSTRIDE + ch + i * 8] = src[i];
    }
    if (t < 128) ksqs[t] = 0.f;
    __syncthreads();

    const int w = t >> 5, lane = t & 31;
    const int m0 = (w >> 2) * 64, n0 = (w & 3) * 32;
    const int gid = lane >> 2, tid2 = lane & 3;
    const int arow = lane & 15, acol = ((lane >> 4) << 3);
    const int brow = lane & 7,  bcol = (((lane >> 3) & 1) << 3);

    float acc[4][4][4];
    #pragma unroll
    for (int i = 0; i < 4; i++)
        #pragma unroll
        for (int j = 0; j < 4; j++)
            #pragma unroll
            for (int c = 0; c < 4; c++) acc[i][j][c] = 0.f;

    #pragma unroll
    for (int ks = 0; ks < 8; ks++) {
        const int k0 = ks * 16;
        uint32_t A[4][4], Bf[4][2];
        #pragma unroll
        for (int ms = 0; ms < 4; ms++)
            ldsm4(A[ms][0], A[ms][1], A[ms][2], A[ms][3],
                  sptr(&kcs[(m0 + ms * 16 + arow) * PSTRIDE + k0 + acol]));
        #pragma unroll
        for (int ns = 0; ns < 4; ns++)
            ldsm2(Bf[ns][0], Bf[ns][1],
                  sptr(&Gs[(n0 + ns * 8 + brow) * PSTRIDE + k0 + bcol]));
        #pragma unroll
        for (int ms = 0; ms < 4; ms++)
            #pragma unroll
            for (int ns = 0; ns < 4; ns++)
                mma16816(acc[ms][ns][0], acc[ms][ns][1], acc[ms][ns][2], acc[ms][ns][3],
                         A[ms][0], A[ms][1], A[ms][2], A[ms][3], Bf[ns][0], Bf[ns][1]);
    }

    #pragma unroll
    for (int ms = 0; ms < 4; ms++) {
        const int rA = m0 + ms * 16 + gid, rB = rA + 8;
        float sA = 0.f, sB = 0.f;
        #pragma unroll
        for (int ns = 0; ns < 4; ns++) {
            const int c0 = n0 + ns * 8 + tid2 * 2;
            sA += acc[ms][ns][0] * __bfloat162float(kcs[rA * PSTRIDE + c0]);
            sA += acc[ms][ns][1] * __bfloat162float(kcs[rA * PSTRIDE + c0 + 1]);
            sB += acc[ms][ns][2] * __bfloat162float(kcs[rB * PSTRIDE + c0]);
            sB += acc[ms][ns][3] * __bfloat162float(kcs[rB * PSTRIDE + c0 + 1]);
        }
        atomicAdd(&ksqs[rA], sA);
        atomicAdd(&ksqs[rB], sB);
    }
    __syncthreads();
    if (t < 128) g_ksq[row0 + t] = ksqs[t];
}

// ---------------- kernel 4: main — FP8 MMA, 128x64 tile, 3 CTAs/SM ----------------
#define KB 4
#define KT 64                              // k-tile cols per step
#define PS8 144
#define QT8_BYTES (128 * PS8)              // 18432 (q tile)
#define KT8_BYTES (KT * PS8)               // 9216 per k buffer
#define SM_KT8    QT8_BYTES
#define SM_NRM    (QT8_BYTES + 2 * KT8_BYTES)
#define SMEM_MAIN (SM_NRM + 2 * 128 * 4 + 2 * KT * 4 + 256)

__global__ void __launch_bounds__(256, 3) k_main(float* __restrict__ out) {
    extern __shared__ char sm[];
    uint8_t* qts  = (uint8_t*)sm;                      // [128][144] e4m3
    uint8_t* kcs  = (uint8_t*)sm + SM_KT8;             // [2][64][144] e4m3, rows permuted
    float*   qsqs = (float*)(sm + SM_NRM);             // [128]
    float*   rqs  = qsqs + 128;                        // [128]
    float*   ksqr = rqs + 128;                         // [2][64]

    const int t = threadIdx.x;                         // 256
    const int kbb = blockIdx.x, qb = blockIdx.y, b = blockIdx.z;
    const int q0 = qb * 128, kbase = kbb * (KT * KB);

    // q tile (once): 2 threads/row
    {
        const int rq = t >> 1, chb = (t & 1) * 64;
        const uint4* s1 = (const uint4*)(g_qt8 + ((size_t)(b * LQ + q0 + rq)) * DC + chb);
        #pragma unroll
        for (int i = 0; i < 4; i++) *(uint4*)(qts + rq * PS8 + chb + i * 16) = s1[i];
    }
    if (t < 128) {
        float qs = g_qsq[b * LQ + q0 + t];
        qsqs[t] = qs;
        rqs[t] = 1.f - fminf(qs, 1.f - EPSF);
    }

    // k tile: 4 threads/row (64 rows x 128B), permuted rows within 16-groups
    const int rk = t >> 2, kchb = (t & 3) * 32;
    const int lk_ = rk & 15;
    const int prk = (rk & ~15) | (((lk_ >> 1) & 1) * 8 + ((lk_ >> 2) << 1) + (lk_ & 1));

    // prefetch k buffer 0
    {
        const uint32_t dst = sptr(kcs + prk * PS8 + kchb);
        const char* src = (const char*)(g_kc8 + ((size_t)(b * LK + kbase + rk)) * DC + kchb);
        cp16(dst, src);
        cp16(dst + 16, src + 16);
        if (t < 16) cp16(sptr(&ksqr[t * 4]), g_ksq + b * LK + kbase + t * 4);
    }
    cp_commit();

    const int w = t >> 5, lane = t & 31;
    const int m0 = (w & 3) * 32, nw0 = (w >> 2) * 32;
    const int gid = lane >> 2, tid2 = lane & 3;
    const int arow = lane & 15, acolb = ((lane >> 4) << 4);
    const int brow16 = (lane & 7) + ((lane >> 4) << 3);
    const int bcolb = (((lane >> 3) & 1) << 4);

    // uniform-denominator constants
    const float N0C = EPSF + EPSF * EPSF;
    const float H0  = 0.5f * N0C;
    const float C0  = LN2F * (2.f - fast_lg2(N0C));
    const float TH  = 50.5f * N0C;
    const float I2N = 2.f * fast_rcp(N0C);

    for (int kb = 0; kb < KB; kb++) {
        cp_wait0();
        __syncthreads();

        if (kb + 1 < KB) {
            const int nb = (kb + 1) & 1;
            const uint32_t dst = sptr(kcs + nb * KT8_BYTES + prk * PS8 + kchb);
            const char* src = (const char*)(g_kc8 + ((size_t)(b * LK + kbase + (kb + 1) * KT + rk)) * DC + kchb);
            cp16(dst, src);
            cp16(dst + 16, src + 16);
            if (t < 16) cp16(sptr(&ksqr[nb * KT + t * 4]),
                             g_ksq + b * LK + kbase + (kb + 1) * KT + t * 4);
            cp_commit();
        }

        const uint8_t* kbuf = kcs + (kb & 1) * KT8_BYTES;
        const float*   kraw = ksqr + (kb & 1) * KT;
        const int k0t = kbase + kb * KT;

        float acc[2][4][4];
        #pragma unroll
        for (int i = 0; i < 2; i++)
            #pragma unroll
            for (int j = 0; j < 4; j++)
                #pragma unroll
                for (int c = 0; c < 4; c++) acc[i][j][c] = 0.f;

        #pragma unroll
        for (int ks = 0; ks < 4; ks++) {
            const int k0b = ks * 32;
            uint32_t A[2][4], Bf[2][4];
            #pragma unroll
            for (int ms = 0; ms < 2; ms++)
                ldsm4(A[ms][0], A[ms][1], A[ms][2], A[ms][3],
                      sptr(qts + (m0 + ms * 16 + arow) * PS8 + k0b + acolb));
            #pragma unroll
            for (int P = 0; P < 2; P++)
                ldsm4(Bf[P][0], Bf[P][1], Bf[P][2], Bf[P][3],
                      sptr(kbuf + (nw0 + P * 16 + brow16) * PS8 + k0b + bcolb));
            #pragma unroll
            for (int ms = 0; ms < 2; ms++)
                #pragma unroll
                for (int P = 0; P < 2; P++) {
                    mma16832fp8(acc[ms][2*P][0], acc[ms][2*P][1], acc[ms][2*P][2], acc[ms][2*P][3],
                                A[ms][0], A[ms][1], A[ms][2], A[ms][3], Bf[P][0], Bf[P][1]);
                    mma16832fp8(acc[ms][2*P+1][0], acc[ms][2*P+1][1], acc[ms][2*P+1][2], acc[ms][2*P+1][3],
                                A[ms][0], A[ms][1], A[ms][2], A[ms][3], Bf[P][2], Bf[P][3]);
                }
        }

        // ---- epilogue ----
        float4 ks4[2];
        ks4[0] = *(const float4*)&kraw[nw0 + 4 * tid2];
        ks4[1] = *(const float4*)&kraw[nw0 + 16 + 4 * tid2];

        bool uni = ks4[0].x >= 1.f - EPSF && ks4[0].y >= 1.f - EPSF &&
                   ks4[0].z >= 1.f - EPSF && ks4[0].w >= 1.f - EPSF &&
                   ks4[1].x >= 1.f - EPSF && ks4[1].y >= 1.f - EPSF &&
                   ks4[1].z >= 1.f - EPSF && ks4[1].w >= 1.f - EPSF;
        #pragma unroll
        for (int ms = 0; ms < 2; ms++) {
            const int rA = m0 + ms * 16 + gid;
            uni = uni && (qsqs[rA] >= 1.f - EPSF) && (qsqs[rA + 8] >= 1.f - EPSF);
        }

        if (uni) {
            #pragma unroll
            for (int ms = 0; ms < 2; ms++) {
                const int rA = m0 + ms * 16 + gid, rB = rA + 8;
                const float aA = qsqs[rA] + H0, aB = qsqs[rB] + H0;
                const size_t baseA = ((size_t)(b * LQ + q0 + rA)) * LK + k0t;
                const size_t baseB = baseA + (size_t)8 * LK;
                #pragma unroll
                for (int P = 0; P < 2; P++) {
                    const int c0 = nw0 + P * 16 + 4 * tid2;
                    const float4 kk = ks4[P];
                    const float ksv[4] = { kk.x, kk.y, kk.z, kk.w };
                    float vA[4] = { acc[ms][2*P][0], acc[ms][2*P][1], acc[ms][2*P+1][0], acc[ms][2*P+1][1] };
                    float vB[4] = { acc[ms][2*P][2], acc[ms][2*P][3], acc[ms][2*P+1][2], acc[ms][2*P+1][3] };

                    float xA[4], xB[4], dA[4], dB[4];
                    bool bad = false;
                    #pragma unroll
                    for (int j = 0; j < 4; j++) {
                        xA[j] = fmaxf(fmaf(-2.f, vA[j], aA + ksv[j]), H0);
                        xB[j] = fmaxf(fmaf(-2.f, vB[j], aB + ksv[j]), H0);
                        bad |= (xA[j] < TH) | (xB[j] < TH);
                        dA[j] = fmaf(fast_lg2(xA[j]), LN2F, C0);
                        dB[j] = fmaf(fast_lg2(xB[j]), LN2F, C0);
                    }
                    if (bad) {   // exact acosh for small-t elements (cold)
                        #pragma unroll
                        for (int j = 0; j < 4; j++) {
                            float tA = (xA[j] - H0) * I2N;
                            float sA = fast_sqrt(fmaf(tA, tA, 2.f * tA));
                            dA[j] = LN2F * fast_lg2(1.f + tA + sA);
                            float tB = (xB[j] - H0) * I2N;
                            float sB = fast_sqrt(fmaf(tB, tB, 2.f * tB));
                            dB[j] = LN2F * fast_lg2(1.f + tB + sB);
                        }
                    }
                    __stcs((float4*)(out + baseA + c0), make_float4(dA[0], dA[1], dA[2], dA[3]));
                    __stcs((float4*)(out + baseB + c0), make_float4(dB[0], dB[1], dB[2], dB[3]));
                }
            }
        } else {
            // general path (cold for this data distribution)
            #pragma unroll
            for (int ms = 0; ms < 2; ms++) {
                const int rA = m0 + ms * 16 + gid, rB = rA + 8;
                const float qsA = qsqs[rA], qsB = qsqs[rB];
                const float rqA = rqs[rA],  rqB = rqs[rB];
                const size_t baseA = ((size_t)(b * LQ + q0 + rA)) * LK + k0t;
                const size_t baseB = baseA + (size_t)8 * LK;
                #pragma unroll
                for (int P = 0; P < 2; P++) {
                    const int c0 = nw0 + P * 16 + 4 * tid2;
                    const float4 kk = ks4[P];
                    const float ksv[4] = { kk.x, kk.y, kk.z, kk.w };
                    float vA[4] = { acc[ms][2*P][0], acc[ms][2*P][1], acc[ms][2*P+1][0], acc[ms][2*P+1][1] };
                    float vB[4] = { acc[ms][2*P][2], acc[ms][2*P][3], acc[ms][2*P+1][2], acc[ms][2*P+1][3] };

                    float dA[4], dB[4];
                    #pragma unroll
                    for (int j = 0; j < 4; j++) {
                        const float rkj = 1.f - fminf(ksv[j], 1.f - EPSF);
                        float uA = 2.f * fmaxf(fmaf(-2.f, vA[j], qsA + ksv[j]), 0.f);
                        float nA = fmaf(rqA, rkj, EPSF);
                        float uB = 2.f * fmaxf(fmaf(-2.f, vB[j], qsB + ksv[j]), 0.f);
                        float nB = fmaf(rqB, rkj, EPSF);
                        if (uA >= 100.f * nA) {
                            dA[j] = LN2F * (1.f + fast_lg2(uA + nA) - fast_lg2(nA));
                        } else {
                            float tA = uA * fast_rcp(nA);
                            float sA = fast_sqrt(fmaf(tA, tA, 2.f * tA));
                            dA[j] = LN2F * fast_lg2(1.f + tA + sA);
                        }
                        if (uB >= 100.f * nB) {
                            dB[j] = LN2F * (1.f + fast_lg2(uB + nB) - fast_lg2(nB));
                        } else {
                            float tB = uB * fast_rcp(nB);
                            float sB = fast_sqrt(fmaf(tB, tB, 2.f * tB));
                            dB[j] = LN2F * fast_lg2(1.f + tB + sB);
                        }
                    }
                    __stcs((float4*)(out + baseA + c0), make_float4(dA[0], dA[1], dA[2], dA[3]));
                    __stcs((float4*)(out + baseB + c0), make_float4(dB[0], dB[1], dB[2], dB[3]));
                }
            }
        }
        __syncthreads();
    }
}

// ---------------- launch ----------------
extern "C" void kernel_launch(void* const* d_in, const int* in_sizes, int n_in,
                              void* d_out, int out_size) {
    const float* q   = (const float*)d_in[0];
    const int*   kq  = (const int*)d_in[1];
    const float* ksc = (const float*)d_in[2];
    const float* kz  = (const float*)d_in[3];
    const float* W   = (const float*)d_in[4];
    float* out = (float*)d_out;
    (void)in_sizes; (void)n_in; (void)out_size;

    cudaFuncSetAttribute(k_prepq, cudaFuncAttributeMaxDynamicSharedMemorySize, SMEM_PREPQ);
    cudaFuncSetAttribute(k_prepk, cudaFuncAttributeMaxDynamicSharedMemorySize, SMEM_PREPK);
    cudaFuncSetAttribute(k_main,  cudaFuncAttributeMaxDynamicSharedMemorySize, SMEM_MAIN);

    k_G<<<DC, 256>>>(W);
    k_prepq<<<(B_ * LQ) / QR, 256, SMEM_PREPQ>>>(q);
    k_prepk<<<(B_ * LK) / 128, 256, SMEM_PREPK>>>(kq, ksc, kz);
    k_main<<<dim3(LK / (KT * KB), LQ / 128, B_), 256, SMEM_MAIN>>>(out);
}